// round 1
// baseline (speedup 1.0000x reference)
#include <cuda_runtime.h>
#include <math.h>

#define B_ 4
#define S_ 2048
#define D_ 1024
#define H_ 16
#define DH_ 64
#define E_ 8
#define DFF_ 4096
#define T_ (B_*S_)          // 8192 tokens

// ---------------- scratch (device globals; no cudaMalloc allowed) ----------
__device__ float g_h[(size_t)T_*D_];            // LN1 out            32 MB
__device__ float g_qkv[(size_t)T_*3*D_];        // qkv                96 MB
__device__ float g_attn[(size_t)T_*D_];         // attention out      32 MB
__device__ float g_x1[(size_t)T_*D_];           // post-attn residual 32 MB
__device__ float g_moein[(size_t)T_*D_];        // LN2 out            32 MB
__device__ float g_he[(size_t)2*T_*DFF_];       // expert hidden     256 MB
__device__ float g_ybuf[(size_t)2*T_*D_];       // expert out         64 MB
__device__ int   g_cnt[E_];
__device__ int   g_exTok[E_*T_];
__device__ int   g_exDst[E_*T_];
__device__ float g_tokW[2*T_];

// ---------------------------------------------------------------- zero cnt
__global__ void zero_cnt_kernel() {
    if (threadIdx.x < E_) g_cnt[threadIdx.x] = 0;
}

// ---------------------------------------------------------------- layernorm
__global__ void ln_kernel(const float* __restrict__ x,
                          const float* __restrict__ g,
                          const float* __restrict__ b,
                          float* __restrict__ out) {
    int row = blockIdx.x;
    int t = threadIdx.x;                       // 256 threads
    const float* xr = x + (size_t)row * D_;
    float v[4];
    float s = 0.f, ss = 0.f;
#pragma unroll
    for (int i = 0; i < 4; i++) {
        v[i] = xr[t + i*256];
        s += v[i]; ss += v[i]*v[i];
    }
#pragma unroll
    for (int m = 16; m; m >>= 1) {
        s  += __shfl_xor_sync(~0u, s, m);
        ss += __shfl_xor_sync(~0u, ss, m);
    }
    __shared__ float rs[8], rss[8];
    if ((t & 31) == 0) { rs[t>>5] = s; rss[t>>5] = ss; }
    __syncthreads();
    float sum = 0.f, sumsq = 0.f;
#pragma unroll
    for (int i = 0; i < 8; i++) { sum += rs[i]; sumsq += rss[i]; }
    float mean = sum * (1.f/D_);
    float var  = sumsq * (1.f/D_) - mean*mean;
    float rstd = rsqrtf(var + 1e-5f);
    float* orow = out + (size_t)row * D_;
#pragma unroll
    for (int i = 0; i < 4; i++) {
        int c = t + i*256;
        orow[c] = (v[i]-mean)*rstd*g[c] + b[c];
    }
}

// ---------------------------------------------------------------- SGEMM
// C[M,N] = act(gather(A)[M,K] @ B[K,N] + bias (+ res))
// 64x64 tile, BK=32, 256 threads, 4x4 per thread.
// gatherA/scatterC: optional row index lists (per blockIdx.z expert).
template<bool GELU, bool RES>
__global__ void sgemm_kernel(const float* __restrict__ A,
                             const float* __restrict__ Bw,
                             const float* __restrict__ bias,
                             const float* __restrict__ res,
                             float* __restrict__ C,
                             int M, int N, int K,
                             const int* __restrict__ gatherA,
                             const int* __restrict__ scatterC,
                             const int* __restrict__ cnt,
                             size_t bStride, int biasStride, int listStride)
{
    int e = blockIdx.z;
    int Me = cnt ? cnt[e] : M;
    int m0 = blockIdx.y * 64;
    if (m0 >= Me) return;
    int n0 = blockIdx.x * 64;

    const float* Bp    = Bw + (size_t)e * bStride;
    const float* biasp = bias ? bias + (size_t)e * biasStride : nullptr;
    const int*   gA    = gatherA  ? gatherA  + (size_t)e * listStride : nullptr;
    const int*   sC    = scatterC ? scatterC + (size_t)e * listStride : nullptr;

    __shared__ __align__(16) float As[32*68];   // [k][m], padded
    __shared__ __align__(16) float Bs[32*64];   // [k][n]

    int tid = threadIdx.x;
    int tx = tid & 15, ty = tid >> 4;

    float acc[4][4] = {};

    // A load mapping: 64 rows x 4 threads, each thread 2 float4 along k
    int mA  = tid >> 2;
    int kq  = (tid & 3) * 4;
    int rowA = m0 + mA;
    const float* Arow = nullptr;
    if (rowA < Me) {
        int gr = gA ? gA[rowA] : rowA;
        Arow = A + (size_t)gr * K;
    }
    // B load mapping: 16 threads per row of 64
    int rB = (tid * 4) >> 6;
    int cB = (tid * 4) & 63;

    for (int k = 0; k < K; k += 32) {
#pragma unroll
        for (int hh = 0; hh < 2; hh++) {
            int kk = kq + hh*16;
            float4 a = Arow ? *(const float4*)(Arow + k + kk)
                            : make_float4(0.f,0.f,0.f,0.f);
            As[(kk+0)*68 + mA] = a.x;
            As[(kk+1)*68 + mA] = a.y;
            As[(kk+2)*68 + mA] = a.z;
            As[(kk+3)*68 + mA] = a.w;
        }
#pragma unroll
        for (int hh = 0; hh < 2; hh++) {
            int kk = rB + hh*16;
            float4 bb = *(const float4*)(Bp + (size_t)(k + kk)*N + n0 + cB);
            *(float4*)(Bs + kk*64 + cB) = bb;
        }
        __syncthreads();
#pragma unroll
        for (int kk = 0; kk < 32; kk++) {
            float4 a = *(const float4*)(As + kk*68 + ty*4);
            float4 b = *(const float4*)(Bs + kk*64 + tx*4);
            float av[4] = {a.x,a.y,a.z,a.w};
            float bv[4] = {b.x,b.y,b.z,b.w};
#pragma unroll
            for (int i = 0; i < 4; i++)
#pragma unroll
                for (int j = 0; j < 4; j++)
                    acc[i][j] = fmaf(av[i], bv[j], acc[i][j]);
        }
        __syncthreads();
    }

#pragma unroll
    for (int i = 0; i < 4; i++) {
        int m = m0 + ty*4 + i;
        if (m >= Me) continue;
        int crow = sC ? sC[m] : m;
        float* Crow = C + (size_t)crow * N + n0 + tx*4;
        const float* Rrow = RES ? (res + (size_t)crow * N + n0 + tx*4) : nullptr;
        float vals[4];
#pragma unroll
        for (int j = 0; j < 4; j++) {
            float v = acc[i][j];
            if (biasp) v += biasp[n0 + tx*4 + j];
            if (RES) v += Rrow[j];
            if (GELU) {
                float u = v;
                v = 0.5f*u*(1.f + tanhf(0.7978845608028654f*(u + 0.044715f*u*u*u)));
            }
            vals[j] = v;
        }
        *(float4*)Crow = make_float4(vals[0],vals[1],vals[2],vals[3]);
    }
}

// ---------------------------------------------------------------- attention
// One block per (q-tile of 64, head, batch). Online softmax, DH=64.
__global__ void attn_kernel(const float* __restrict__ qkv, float* __restrict__ o)
{
    __shared__ __align__(16) float QT[64*64];   // [d][q], pre-scaled
    __shared__ __align__(16) float KT[64*64];   // [d][k], reused for P[k][q]
    __shared__ __align__(16) float Vs[64*64];   // [k][d]

    int qt = blockIdx.x, h = blockIdx.y, b = blockIdx.z;
    int tid = threadIdx.x;
    int tx = tid & 15, ty = tid >> 4;
    size_t base = (size_t)b * S_ * (3*D_);

#pragma unroll
    for (int rep = 0; rep < 4; rep++) {
        int idx = rep*1024 + tid*4;
        int r = idx >> 6, d0 = idx & 63;
        const float* p = qkv + base + (size_t)(qt*64 + r)*(3*D_) + h*DH_ + d0;
        float4 q = *(const float4*)p;
        QT[(d0+0)*64 + r] = q.x * 0.125f;
        QT[(d0+1)*64 + r] = q.y * 0.125f;
        QT[(d0+2)*64 + r] = q.z * 0.125f;
        QT[(d0+3)*64 + r] = q.w * 0.125f;
    }

    float m_[4], l_[4], oacc[4][4];
#pragma unroll
    for (int i = 0; i < 4; i++) {
        m_[i] = -1e30f; l_[i] = 0.f;
#pragma unroll
        for (int j = 0; j < 4; j++) oacc[i][j] = 0.f;
    }

    for (int kt = 0; kt < S_/64; kt++) {
#pragma unroll
        for (int rep = 0; rep < 4; rep++) {
            int idx = rep*1024 + tid*4;
            int r = idx >> 6, d0 = idx & 63;
            size_t rowoff = base + (size_t)(kt*64 + r)*(3*D_) + h*DH_ + d0;
            float4 kv = *(const float4*)(qkv + rowoff + D_);
            KT[(d0+0)*64 + r] = kv.x;
            KT[(d0+1)*64 + r] = kv.y;
            KT[(d0+2)*64 + r] = kv.z;
            KT[(d0+3)*64 + r] = kv.w;
            float4 vv = *(const float4*)(qkv + rowoff + 2*D_);
            *(float4*)(Vs + r*64 + d0) = vv;
        }
        __syncthreads();

        float s[4][4] = {};
#pragma unroll
        for (int kk = 0; kk < 64; kk++) {
            float4 a = *(const float4*)(QT + kk*64 + ty*4);
            float4 bb = *(const float4*)(KT + kk*64 + tx*4);
            float av[4] = {a.x,a.y,a.z,a.w};
            float bv[4] = {bb.x,bb.y,bb.z,bb.w};
#pragma unroll
            for (int i = 0; i < 4; i++)
#pragma unroll
                for (int j = 0; j < 4; j++)
                    s[i][j] = fmaf(av[i], bv[j], s[i][j]);
        }
        __syncthreads();   // all reads of KT done before overwrite with P

#pragma unroll
        for (int i = 0; i < 4; i++) {
            float rm = fmaxf(fmaxf(s[i][0], s[i][1]), fmaxf(s[i][2], s[i][3]));
#pragma unroll
            for (int msk = 1; msk < 16; msk <<= 1)
                rm = fmaxf(rm, __shfl_xor_sync(~0u, rm, msk));
            float mn = fmaxf(m_[i], rm);
            float alpha = __expf(m_[i] - mn);
            float rsum = 0.f;
#pragma unroll
            for (int j = 0; j < 4; j++) { s[i][j] = __expf(s[i][j] - mn); rsum += s[i][j]; }
#pragma unroll
            for (int msk = 1; msk < 16; msk <<= 1)
                rsum += __shfl_xor_sync(~0u, rsum, msk);
            l_[i] = l_[i]*alpha + rsum;
            m_[i] = mn;
#pragma unroll
            for (int j = 0; j < 4; j++) oacc[i][j] *= alpha;
        }
        // write P into KT buffer: P[k=tx*4+j][q=ty*4..+3]
#pragma unroll
        for (int j = 0; j < 4; j++)
            *(float4*)(KT + (tx*4+j)*64 + ty*4) =
                make_float4(s[0][j], s[1][j], s[2][j], s[3][j]);
        __syncthreads();

#pragma unroll
        for (int c = 0; c < 64; c++) {
            float4 pv = *(const float4*)(KT + c*64 + ty*4);
            float4 vv = *(const float4*)(Vs + c*64 + tx*4);
            float pva[4] = {pv.x,pv.y,pv.z,pv.w};
            float vva[4] = {vv.x,vv.y,vv.z,vv.w};
#pragma unroll
            for (int i = 0; i < 4; i++)
#pragma unroll
                for (int j = 0; j < 4; j++)
                    oacc[i][j] = fmaf(pva[i], vva[j], oacc[i][j]);
        }
        __syncthreads();   // Vs/P reads done before next tile load
    }

#pragma unroll
    for (int i = 0; i < 4; i++) {
        float inv = 1.f / l_[i];
        int tok = b*S_ + qt*64 + ty*4 + i;
        *(float4*)(o + (size_t)tok*D_ + h*DH_ + tx*4) =
            make_float4(oacc[i][0]*inv, oacc[i][1]*inv,
                        oacc[i][2]*inv, oacc[i][3]*inv);
    }
}

// ---------------------------------------------------------------- gate/top2
__global__ void gate_kernel(const float* __restrict__ xin,
                            const float* __restrict__ wg)
{
    int t = blockIdx.x;
    int tid = threadIdx.x;     // 128
    const float* xr = xin + (size_t)t * D_;
    float acc[E_] = {};
    for (int d = tid; d < D_; d += 128) {
        float xv = xr[d];
        const float* w = wg + d*E_;
#pragma unroll
        for (int e = 0; e < E_; e++) acc[e] = fmaf(xv, w[e], acc[e]);
    }
#pragma unroll
    for (int e = 0; e < E_; e++)
#pragma unroll
        for (int msk = 16; msk; msk >>= 1)
            acc[e] += __shfl_xor_sync(~0u, acc[e], msk);
    __shared__ float red[4][E_];
    if ((tid & 31) == 0)
#pragma unroll
        for (int e = 0; e < E_; e++) red[tid>>5][e] = acc[e];
    __syncthreads();
    if (tid == 0) {
        float lg[E_];
#pragma unroll
        for (int e = 0; e < E_; e++)
            lg[e] = red[0][e] + red[1][e] + red[2][e] + red[3][e];
        int i0 = 0;
#pragma unroll
        for (int e = 1; e < E_; e++) if (lg[e] > lg[i0]) i0 = e;
        int i1 = -1;
#pragma unroll
        for (int e = 0; e < E_; e++)
            if (e != i0 && (i1 < 0 || lg[e] > lg[i1])) i1 = e;
        float d10 = __expf(lg[i1] - lg[i0]);        // <= 1
        float w0 = 1.f / (1.f + d10);
        float w1 = d10 * w0;
        g_tokW[2*t]   = w0;
        g_tokW[2*t+1] = w1;
        int p0 = atomicAdd(&g_cnt[i0], 1);
        g_exTok[i0*T_ + p0] = t;  g_exDst[i0*T_ + p0] = 2*t;
        int p1 = atomicAdd(&g_cnt[i1], 1);
        g_exTok[i1*T_ + p1] = t;  g_exDst[i1*T_ + p1] = 2*t+1;
    }
}

// ---------------------------------------------------------------- combine
__global__ void combine_kernel(const float* __restrict__ x1,
                               float* __restrict__ out)
{
    size_t idx = ((size_t)blockIdx.x * 256 + threadIdx.x) * 4;
    if (idx >= (size_t)T_*D_) return;
    int t = (int)(idx >> 10);
    int c = (int)(idx & (D_-1));
    float w0 = g_tokW[2*t], w1 = g_tokW[2*t+1];
    float4 a  = *(const float4*)(x1 + idx);
    float4 y0 = *(const float4*)(g_ybuf + (size_t)(2*t)*D_ + c);
    float4 y1 = *(const float4*)(g_ybuf + (size_t)(2*t+1)*D_ + c);
    float4 r;
    r.x = a.x + w0*y0.x + w1*y1.x;
    r.y = a.y + w0*y0.y + w1*y1.y;
    r.z = a.z + w0*y0.z + w1*y1.z;
    r.w = a.w + w0*y0.w + w1*y1.w;
    *(float4*)(out + idx) = r;
}

// ---------------------------------------------------------------- launch
extern "C" void kernel_launch(void* const* d_in, const int* in_sizes, int n_in,
                              void* d_out, int out_size)
{
    const float* x      = (const float*)d_in[0];
    const float* ln1_g  = (const float*)d_in[1];
    const float* ln1_b  = (const float*)d_in[2];
    const float* ln2_g  = (const float*)d_in[3];
    const float* ln2_b  = (const float*)d_in[4];
    const float* w_qkv  = (const float*)d_in[5];
    const float* b_qkv  = (const float*)d_in[6];
    const float* w_out  = (const float*)d_in[7];
    const float* b_out  = (const float*)d_in[8];
    const float* w_gate = (const float*)d_in[9];
    const float* w1     = (const float*)d_in[10];
    const float* b1     = (const float*)d_in[11];
    const float* w2     = (const float*)d_in[12];
    const float* b2     = (const float*)d_in[13];
    float* out = (float*)d_out;

    float *p_h, *p_qkv, *p_attn, *p_x1, *p_moein, *p_he, *p_ybuf, *p_tokW;
    int *p_exTok, *p_exDst, *p_cnt;
    cudaGetSymbolAddress((void**)&p_h,     g_h);
    cudaGetSymbolAddress((void**)&p_qkv,   g_qkv);
    cudaGetSymbolAddress((void**)&p_attn,  g_attn);
    cudaGetSymbolAddress((void**)&p_x1,    g_x1);
    cudaGetSymbolAddress((void**)&p_moein, g_moein);
    cudaGetSymbolAddress((void**)&p_he,    g_he);
    cudaGetSymbolAddress((void**)&p_ybuf,  g_ybuf);
    cudaGetSymbolAddress((void**)&p_tokW,  g_tokW);
    cudaGetSymbolAddress((void**)&p_exTok, g_exTok);
    cudaGetSymbolAddress((void**)&p_exDst, g_exDst);
    cudaGetSymbolAddress((void**)&p_cnt,   g_cnt);

    zero_cnt_kernel<<<1, 32>>>();

    // LN1
    ln_kernel<<<T_, 256>>>(x, ln1_g, ln1_b, p_h);

    // QKV: [8192,1024] @ [1024,3072] + b
    sgemm_kernel<false,false><<<dim3(3*D_/64, T_/64, 1), 256>>>(
        p_h, w_qkv, b_qkv, nullptr, p_qkv,
        T_, 3*D_, D_, nullptr, nullptr, nullptr, 0, 0, 0);

    // attention
    attn_kernel<<<dim3(S_/64, H_, B_), 256>>>(p_qkv, p_attn);

    // out-proj + residual: x1 = x + attn @ w_out + b_out
    sgemm_kernel<false,true><<<dim3(D_/64, T_/64, 1), 256>>>(
        p_attn, w_out, b_out, x, p_x1,
        T_, D_, D_, nullptr, nullptr, nullptr, 0, 0, 0);

    // LN2
    ln_kernel<<<T_, 256>>>(p_x1, ln2_g, ln2_b, p_moein);

    // gate + routing
    gate_kernel<<<T_, 128>>>(p_moein, w_gate);

    // expert GEMM1: he = gelu(gather(moe_in) @ w1[e] + b1[e])
    sgemm_kernel<true,false><<<dim3(DFF_/64, T_/64, E_), 256>>>(
        p_moein, w1, b1, nullptr, p_he,
        0, DFF_, D_, p_exTok, p_exDst, p_cnt,
        (size_t)D_*DFF_, DFF_, T_);

    // expert GEMM2: ybuf = gather(he) @ w2[e] + b2[e]
    sgemm_kernel<false,false><<<dim3(D_/64, T_/64, E_), 256>>>(
        p_he, w2, b2, nullptr, p_ybuf,
        0, D_, DFF_, p_exDst, p_exDst, p_cnt,
        (size_t)DFF_*D_, D_, T_);

    // combine: out = x1 + w0*y0 + w1*y1
    combine_kernel<<<(T_*D_/4 + 255)/256, 256>>>(p_x1, out);
}

// round 2
// speedup vs baseline: 1.6520x; 1.6520x over previous
#include <cuda_runtime.h>
#include <math.h>

#define B_ 4
#define S_ 2048
#define D_ 1024
#define H_ 16
#define DH_ 64
#define E_ 8
#define DFF_ 4096
#define T_ (B_*S_)          // 8192 tokens

// ---------------- scratch (device globals; no cudaMalloc allowed) ----------
__device__ float g_h[(size_t)T_*D_];            // LN1 out            32 MB
__device__ float g_qkv[(size_t)T_*3*D_];        // qkv                96 MB
__device__ float g_attn[(size_t)T_*D_];         // attention out      32 MB
__device__ float g_x1[(size_t)T_*D_];           // post-attn residual 32 MB
__device__ float g_moein[(size_t)T_*D_];        // LN2 out            32 MB
__device__ float g_he[(size_t)2*T_*DFF_];       // expert hidden     256 MB
__device__ float g_ybuf[(size_t)2*T_*D_];       // expert out         64 MB
__device__ int   g_cnt[E_];
__device__ int   g_exTok[E_*T_];
__device__ int   g_exDst[E_*T_];
__device__ float g_tokW[2*T_];

// ---------------------------------------------------------------- zero cnt
__global__ void zero_cnt_kernel() {
    if (threadIdx.x < E_) g_cnt[threadIdx.x] = 0;
}

// ---------------------------------------------------------------- layernorm
__global__ void ln_kernel(const float* __restrict__ x,
                          const float* __restrict__ g,
                          const float* __restrict__ b,
                          float* __restrict__ out) {
    int row = blockIdx.x;
    int t = threadIdx.x;                       // 256 threads
    const float* xr = x + (size_t)row * D_;
    float v[4];
    float s = 0.f, ss = 0.f;
#pragma unroll
    for (int i = 0; i < 4; i++) {
        v[i] = xr[t + i*256];
        s += v[i]; ss += v[i]*v[i];
    }
#pragma unroll
    for (int m = 16; m; m >>= 1) {
        s  += __shfl_xor_sync(~0u, s, m);
        ss += __shfl_xor_sync(~0u, ss, m);
    }
    __shared__ float rs[8], rss[8];
    if ((t & 31) == 0) { rs[t>>5] = s; rss[t>>5] = ss; }
    __syncthreads();
    float sum = 0.f, sumsq = 0.f;
#pragma unroll
    for (int i = 0; i < 8; i++) { sum += rs[i]; sumsq += rss[i]; }
    float mean = sum * (1.f/D_);
    float var  = sumsq * (1.f/D_) - mean*mean;
    float rstd = rsqrtf(var + 1e-5f);
    float* orow = out + (size_t)row * D_;
#pragma unroll
    for (int i = 0; i < 4; i++) {
        int c = t + i*256;
        orow[c] = (v[i]-mean)*rstd*g[c] + b[c];
    }
}

// ---------------------------------------------------------------- SGEMM (fp32, attention path)
template<bool GELU, bool RES>
__global__ void sgemm_kernel(const float* __restrict__ A,
                             const float* __restrict__ Bw,
                             const float* __restrict__ bias,
                             const float* __restrict__ res,
                             float* __restrict__ C,
                             int M, int N, int K)
{
    int m0 = blockIdx.y * 64;
    int n0 = blockIdx.x * 64;

    __shared__ __align__(16) float As[32*68];   // [k][m], padded
    __shared__ __align__(16) float Bs[32*64];   // [k][n]

    int tid = threadIdx.x;
    int tx = tid & 15, ty = tid >> 4;

    float acc[4][4] = {};

    int mA  = tid >> 2;
    int kq  = (tid & 3) * 4;
    int rowA = m0 + mA;
    const float* Arow = A + (size_t)rowA * K;
    int rB = (tid * 4) >> 6;
    int cB = (tid * 4) & 63;

    for (int k = 0; k < K; k += 32) {
#pragma unroll
        for (int hh = 0; hh < 2; hh++) {
            int kk = kq + hh*16;
            float4 a = *(const float4*)(Arow + k + kk);
            As[(kk+0)*68 + mA] = a.x;
            As[(kk+1)*68 + mA] = a.y;
            As[(kk+2)*68 + mA] = a.z;
            As[(kk+3)*68 + mA] = a.w;
        }
#pragma unroll
        for (int hh = 0; hh < 2; hh++) {
            int kk = rB + hh*16;
            float4 bb = *(const float4*)(Bw + (size_t)(k + kk)*N + n0 + cB);
            *(float4*)(Bs + kk*64 + cB) = bb;
        }
        __syncthreads();
#pragma unroll
        for (int kk = 0; kk < 32; kk++) {
            float4 a = *(const float4*)(As + kk*68 + ty*4);
            float4 b = *(const float4*)(Bs + kk*64 + tx*4);
            float av[4] = {a.x,a.y,a.z,a.w};
            float bv[4] = {b.x,b.y,b.z,b.w};
#pragma unroll
            for (int i = 0; i < 4; i++)
#pragma unroll
                for (int j = 0; j < 4; j++)
                    acc[i][j] = fmaf(av[i], bv[j], acc[i][j]);
        }
        __syncthreads();
    }

#pragma unroll
    for (int i = 0; i < 4; i++) {
        int m = m0 + ty*4 + i;
        float* Crow = C + (size_t)m * N + n0 + tx*4;
        const float* Rrow = RES ? (res + (size_t)m * N + n0 + tx*4) : nullptr;
        float vals[4];
#pragma unroll
        for (int j = 0; j < 4; j++) {
            float v = acc[i][j];
            v += bias[n0 + tx*4 + j];
            if (RES) v += Rrow[j];
            if (GELU) {
                float u = v;
                v = 0.5f*u*(1.f + tanhf(0.7978845608028654f*(u + 0.044715f*u*u*u)));
            }
            vals[j] = v;
        }
        *(float4*)Crow = make_float4(vals[0],vals[1],vals[2],vals[3]);
    }
}

// ---------------------------------------------------------------- MoE expert GEMM (tf32 mma)
// C[gather(M),N] = act(gather(A)[M,K] @ B[K,N] + bias), scattered rows.
// Block tile 128x64x32; 8 warps (4M x 2N); warp tile 32x32 = 2x4 mma(16x8x8).
__device__ __forceinline__ unsigned f2tf32(float x) {
    unsigned r;
    asm("cvt.rna.tf32.f32 %0, %1;" : "=r"(r) : "f"(x));
    return r;
}

template<bool GELU>
__global__ void __launch_bounds__(256, 2)
moe_mma_kernel(const float* __restrict__ A,
               const float* __restrict__ Bw,
               const float* __restrict__ bias,
               float* __restrict__ C,
               int N, int K,
               const int* __restrict__ gatherA,
               const int* __restrict__ scatterC,
               const int* __restrict__ cnt,
               size_t bStride, int biasStride, int listStride)
{
    int e = blockIdx.z;
    int Me = cnt[e];
    int m0 = blockIdx.y * 128;
    if (m0 >= Me) return;
    int n0 = blockIdx.x * 64;

    const float* Bp    = Bw + (size_t)e * bStride;
    const float* biasp = bias + (size_t)e * biasStride;
    const int*   gA    = gatherA  + (size_t)e * listStride;
    const int*   sC    = scatterC + (size_t)e * listStride;

    __shared__ __align__(16) float As[128*36];   // [m][k], stride 36
    __shared__ __align__(16) float Bs[32*68];    // [k][n], stride 68

    int tid  = threadIdx.x;
    int lane = tid & 31;
    int warp = tid >> 5;
    int wm = warp & 3;          // 0..3 -> M offset wm*32
    int wn = warp >> 2;         // 0..1 -> N offset wn*32

    // ---- global A pointers (gathered rows), 4 chunks per thread ----
    const float* aPtr[4];
    int aSrow[4];
    int ac4 = (tid & 7) * 4;
#pragma unroll
    for (int i = 0; i < 4; i++) {
        int r = (tid + i*256) >> 3;      // 0..127
        aSrow[i] = r;
        int rowA = m0 + r;
        aPtr[i] = (rowA < Me) ? (A + (size_t)gA[rowA] * K + ac4) : nullptr;
    }
    // ---- global B pointers, 2 chunks per thread ----
    int bn4 = (tid & 15) * 4;
    int bk[2] = { tid >> 4, (tid >> 4) + 16 };
    const float* bPtr = Bp + n0 + bn4;

    float4 pa[4], pb[2];
    const float4 z4 = make_float4(0.f,0.f,0.f,0.f);

#define LOADG(k0)                                                         \
    {                                                                     \
        _Pragma("unroll")                                                 \
        for (int i = 0; i < 4; i++)                                       \
            pa[i] = aPtr[i] ? *(const float4*)(aPtr[i] + (k0)) : z4;      \
        _Pragma("unroll")                                                 \
        for (int i = 0; i < 2; i++)                                       \
            pb[i] = *(const float4*)(bPtr + (size_t)((k0) + bk[i]) * N);  \
    }
#define STORES()                                                          \
    {                                                                     \
        _Pragma("unroll")                                                 \
        for (int i = 0; i < 4; i++) {                                     \
            float* p = As + aSrow[i]*36 + ac4;                            \
            p[0] = __uint_as_float(f2tf32(pa[i].x));                      \
            p[1] = __uint_as_float(f2tf32(pa[i].y));                      \
            p[2] = __uint_as_float(f2tf32(pa[i].z));                      \
            p[3] = __uint_as_float(f2tf32(pa[i].w));                      \
        }                                                                 \
        _Pragma("unroll")                                                 \
        for (int i = 0; i < 2; i++) {                                     \
            float* p = Bs + bk[i]*68 + bn4;                               \
            p[0] = __uint_as_float(f2tf32(pb[i].x));                      \
            p[1] = __uint_as_float(f2tf32(pb[i].y));                      \
            p[2] = __uint_as_float(f2tf32(pb[i].z));                      \
            p[3] = __uint_as_float(f2tf32(pb[i].w));                      \
        }                                                                 \
    }

    float acc[2][4][4];
#pragma unroll
    for (int mi = 0; mi < 2; mi++)
#pragma unroll
        for (int ni = 0; ni < 4; ni++)
#pragma unroll
            for (int j = 0; j < 4; j++) acc[mi][ni][j] = 0.f;

    int fr = lane >> 2;     // 0..7
    int fc = lane & 3;      // 0..3

    LOADG(0);
    STORES();
    __syncthreads();

    for (int k0 = 0; k0 < K; k0 += 32) {
        bool more = (k0 + 32) < K;
        if (more) LOADG(k0 + 32);

#pragma unroll
        for (int kk8 = 0; kk8 < 4; kk8++) {
            int kk = kk8 * 8;
            unsigned af[2][4], bf[4][2];
#pragma unroll
            for (int mi = 0; mi < 2; mi++) {
                int rb = wm*32 + mi*16;
                af[mi][0] = __float_as_uint(As[(rb + fr    )*36 + kk + fc    ]);
                af[mi][1] = __float_as_uint(As[(rb + fr + 8)*36 + kk + fc    ]);
                af[mi][2] = __float_as_uint(As[(rb + fr    )*36 + kk + fc + 4]);
                af[mi][3] = __float_as_uint(As[(rb + fr + 8)*36 + kk + fc + 4]);
            }
#pragma unroll
            for (int ni = 0; ni < 4; ni++) {
                int cb = wn*32 + ni*8;
                bf[ni][0] = __float_as_uint(Bs[(kk + fc    )*68 + cb + fr]);
                bf[ni][1] = __float_as_uint(Bs[(kk + fc + 4)*68 + cb + fr]);
            }
#pragma unroll
            for (int mi = 0; mi < 2; mi++)
#pragma unroll
                for (int ni = 0; ni < 4; ni++) {
                    float* c = acc[mi][ni];
                    asm volatile(
                        "mma.sync.aligned.m16n8k8.row.col.f32.tf32.tf32.f32 "
                        "{%0,%1,%2,%3}, {%4,%5,%6,%7}, {%8,%9}, {%0,%1,%2,%3};\n"
                        : "+f"(c[0]), "+f"(c[1]), "+f"(c[2]), "+f"(c[3])
                        : "r"(af[mi][0]), "r"(af[mi][1]), "r"(af[mi][2]), "r"(af[mi][3]),
                          "r"(bf[ni][0]), "r"(bf[ni][1]));
                }
        }
        __syncthreads();
        if (more) {
            STORES();
            __syncthreads();
        }
    }

    // ---- epilogue: bias (+gelu), scatter rows ----
#pragma unroll
    for (int mi = 0; mi < 2; mi++) {
        int rbase = m0 + wm*32 + mi*16 + fr;
#pragma unroll
        for (int half = 0; half < 2; half++) {
            int m = rbase + half*8;
            if (m >= Me) continue;
            int crow = sC[m];
#pragma unroll
            for (int ni = 0; ni < 4; ni++) {
                int n = n0 + wn*32 + ni*8 + fc*2;
                float v0 = acc[mi][ni][half*2 + 0] + biasp[n];
                float v1 = acc[mi][ni][half*2 + 1] + biasp[n+1];
                if (GELU) {
                    float u = v0;
                    v0 = 0.5f*u*(1.f + tanhf(0.7978845608028654f*(u + 0.044715f*u*u*u)));
                    u = v1;
                    v1 = 0.5f*u*(1.f + tanhf(0.7978845608028654f*(u + 0.044715f*u*u*u)));
                }
                *(float2*)(C + (size_t)crow * N + n) = make_float2(v0, v1);
            }
        }
    }
#undef LOADG
#undef STORES
}

// ---------------------------------------------------------------- attention
__global__ void attn_kernel(const float* __restrict__ qkv, float* __restrict__ o)
{
    __shared__ __align__(16) float QT[64*64];   // [d][q], pre-scaled
    __shared__ __align__(16) float KT[64*64];   // [d][k], reused for P[k][q]
    __shared__ __align__(16) float Vs[64*64];   // [k][d]

    int qt = blockIdx.x, h = blockIdx.y, b = blockIdx.z;
    int tid = threadIdx.x;
    int tx = tid & 15, ty = tid >> 4;
    size_t base = (size_t)b * S_ * (3*D_);

#pragma unroll
    for (int rep = 0; rep < 4; rep++) {
        int idx = rep*1024 + tid*4;
        int r = idx >> 6, d0 = idx & 63;
        const float* p = qkv + base + (size_t)(qt*64 + r)*(3*D_) + h*DH_ + d0;
        float4 q = *(const float4*)p;
        QT[(d0+0)*64 + r] = q.x * 0.125f;
        QT[(d0+1)*64 + r] = q.y * 0.125f;
        QT[(d0+2)*64 + r] = q.z * 0.125f;
        QT[(d0+3)*64 + r] = q.w * 0.125f;
    }

    float m_[4], l_[4], oacc[4][4];
#pragma unroll
    for (int i = 0; i < 4; i++) {
        m_[i] = -1e30f; l_[i] = 0.f;
#pragma unroll
        for (int j = 0; j < 4; j++) oacc[i][j] = 0.f;
    }

    for (int kt = 0; kt < S_/64; kt++) {
#pragma unroll
        for (int rep = 0; rep < 4; rep++) {
            int idx = rep*1024 + tid*4;
            int r = idx >> 6, d0 = idx & 63;
            size_t rowoff = base + (size_t)(kt*64 + r)*(3*D_) + h*DH_ + d0;
            float4 kv = *(const float4*)(qkv + rowoff + D_);
            KT[(d0+0)*64 + r] = kv.x;
            KT[(d0+1)*64 + r] = kv.y;
            KT[(d0+2)*64 + r] = kv.z;
            KT[(d0+3)*64 + r] = kv.w;
            float4 vv = *(const float4*)(qkv + rowoff + 2*D_);
            *(float4*)(Vs + r*64 + d0) = vv;
        }
        __syncthreads();

        float s[4][4] = {};
#pragma unroll
        for (int kk = 0; kk < 64; kk++) {
            float4 a = *(const float4*)(QT + kk*64 + ty*4);
            float4 bb = *(const float4*)(KT + kk*64 + tx*4);
            float av[4] = {a.x,a.y,a.z,a.w};
            float bv[4] = {bb.x,bb.y,bb.z,bb.w};
#pragma unroll
            for (int i = 0; i < 4; i++)
#pragma unroll
                for (int j = 0; j < 4; j++)
                    s[i][j] = fmaf(av[i], bv[j], s[i][j]);
        }
        __syncthreads();

#pragma unroll
        for (int i = 0; i < 4; i++) {
            float rm = fmaxf(fmaxf(s[i][0], s[i][1]), fmaxf(s[i][2], s[i][3]));
#pragma unroll
            for (int msk = 1; msk < 16; msk <<= 1)
                rm = fmaxf(rm, __shfl_xor_sync(~0u, rm, msk));
            float mn = fmaxf(m_[i], rm);
            float alpha = __expf(m_[i] - mn);
            float rsum = 0.f;
#pragma unroll
            for (int j = 0; j < 4; j++) { s[i][j] = __expf(s[i][j] - mn); rsum += s[i][j]; }
#pragma unroll
            for (int msk = 1; msk < 16; msk <<= 1)
                rsum += __shfl_xor_sync(~0u, rsum, msk);
            l_[i] = l_[i]*alpha + rsum;
            m_[i] = mn;
#pragma unroll
            for (int j = 0; j < 4; j++) oacc[i][j] *= alpha;
        }
#pragma unroll
        for (int j = 0; j < 4; j++)
            *(float4*)(KT + (tx*4+j)*64 + ty*4) =
                make_float4(s[0][j], s[1][j], s[2][j], s[3][j]);
        __syncthreads();

#pragma unroll
        for (int c = 0; c < 64; c++) {
            float4 pv = *(const float4*)(KT + c*64 + ty*4);
            float4 vv = *(const float4*)(Vs + c*64 + tx*4);
            float pva[4] = {pv.x,pv.y,pv.z,pv.w};
            float vva[4] = {vv.x,vv.y,vv.z,vv.w};
#pragma unroll
            for (int i = 0; i < 4; i++)
#pragma unroll
                for (int j = 0; j < 4; j++)
                    oacc[i][j] = fmaf(pva[i], vva[j], oacc[i][j]);
        }
        __syncthreads();
    }

#pragma unroll
    for (int i = 0; i < 4; i++) {
        float inv = 1.f / l_[i];
        int tok = b*S_ + qt*64 + ty*4 + i;
        *(float4*)(o + (size_t)tok*D_ + h*DH_ + tx*4) =
            make_float4(oacc[i][0]*inv, oacc[i][1]*inv,
                        oacc[i][2]*inv, oacc[i][3]*inv);
    }
}

// ---------------------------------------------------------------- gate/top2
__global__ void gate_kernel(const float* __restrict__ xin,
                            const float* __restrict__ wg)
{
    int t = blockIdx.x;
    int tid = threadIdx.x;     // 128
    const float* xr = xin + (size_t)t * D_;
    float acc[E_] = {};
    for (int d = tid; d < D_; d += 128) {
        float xv = xr[d];
        const float* w = wg + d*E_;
#pragma unroll
        for (int e = 0; e < E_; e++) acc[e] = fmaf(xv, w[e], acc[e]);
    }
#pragma unroll
    for (int e = 0; e < E_; e++)
#pragma unroll
        for (int msk = 16; msk; msk >>= 1)
            acc[e] += __shfl_xor_sync(~0u, acc[e], msk);
    __shared__ float red[4][E_];
    if ((tid & 31) == 0)
#pragma unroll
        for (int e = 0; e < E_; e++) red[tid>>5][e] = acc[e];
    __syncthreads();
    if (tid == 0) {
        float lg[E_];
#pragma unroll
        for (int e = 0; e < E_; e++)
            lg[e] = red[0][e] + red[1][e] + red[2][e] + red[3][e];
        int i0 = 0;
#pragma unroll
        for (int e = 1; e < E_; e++) if (lg[e] > lg[i0]) i0 = e;
        int i1 = -1;
#pragma unroll
        for (int e = 0; e < E_; e++)
            if (e != i0 && (i1 < 0 || lg[e] > lg[i1])) i1 = e;
        float d10 = __expf(lg[i1] - lg[i0]);        // <= 1
        float w0 = 1.f / (1.f + d10);
        float w1 = d10 * w0;
        g_tokW[2*t]   = w0;
        g_tokW[2*t+1] = w1;
        int p0 = atomicAdd(&g_cnt[i0], 1);
        g_exTok[i0*T_ + p0] = t;  g_exDst[i0*T_ + p0] = 2*t;
        int p1 = atomicAdd(&g_cnt[i1], 1);
        g_exTok[i1*T_ + p1] = t;  g_exDst[i1*T_ + p1] = 2*t+1;
    }
}

// ---------------------------------------------------------------- combine
__global__ void combine_kernel(const float* __restrict__ x1,
                               float* __restrict__ out)
{
    size_t idx = ((size_t)blockIdx.x * 256 + threadIdx.x) * 4;
    if (idx >= (size_t)T_*D_) return;
    int t = (int)(idx >> 10);
    int c = (int)(idx & (D_-1));
    float w0 = g_tokW[2*t], w1 = g_tokW[2*t+1];
    float4 a  = *(const float4*)(x1 + idx);
    float4 y0 = *(const float4*)(g_ybuf + (size_t)(2*t)*D_ + c);
    float4 y1 = *(const float4*)(g_ybuf + (size_t)(2*t+1)*D_ + c);
    float4 r;
    r.x = a.x + w0*y0.x + w1*y1.x;
    r.y = a.y + w0*y0.y + w1*y1.y;
    r.z = a.z + w0*y0.z + w1*y1.z;
    r.w = a.w + w0*y0.w + w1*y1.w;
    *(float4*)(out + idx) = r;
}

// ---------------------------------------------------------------- launch
extern "C" void kernel_launch(void* const* d_in, const int* in_sizes, int n_in,
                              void* d_out, int out_size)
{
    const float* x      = (const float*)d_in[0];
    const float* ln1_g  = (const float*)d_in[1];
    const float* ln1_b  = (const float*)d_in[2];
    const float* ln2_g  = (const float*)d_in[3];
    const float* ln2_b  = (const float*)d_in[4];
    const float* w_qkv  = (const float*)d_in[5];
    const float* b_qkv  = (const float*)d_in[6];
    const float* w_out  = (const float*)d_in[7];
    const float* b_out  = (const float*)d_in[8];
    const float* w_gate = (const float*)d_in[9];
    const float* w1     = (const float*)d_in[10];
    const float* b1     = (const float*)d_in[11];
    const float* w2     = (const float*)d_in[12];
    const float* b2     = (const float*)d_in[13];
    float* out = (float*)d_out;

    float *p_h, *p_qkv, *p_attn, *p_x1, *p_moein, *p_he, *p_ybuf;
    int *p_exTok, *p_exDst, *p_cnt;
    cudaGetSymbolAddress((void**)&p_h,     g_h);
    cudaGetSymbolAddress((void**)&p_qkv,   g_qkv);
    cudaGetSymbolAddress((void**)&p_attn,  g_attn);
    cudaGetSymbolAddress((void**)&p_x1,    g_x1);
    cudaGetSymbolAddress((void**)&p_moein, g_moein);
    cudaGetSymbolAddress((void**)&p_he,    g_he);
    cudaGetSymbolAddress((void**)&p_ybuf,  g_ybuf);
    cudaGetSymbolAddress((void**)&p_exTok, g_exTok);
    cudaGetSymbolAddress((void**)&p_exDst, g_exDst);
    cudaGetSymbolAddress((void**)&p_cnt,   g_cnt);

    zero_cnt_kernel<<<1, 32>>>();

    // LN1
    ln_kernel<<<T_, 256>>>(x, ln1_g, ln1_b, p_h);

    // QKV: [8192,1024] @ [1024,3072] + b   (fp32 — protects routing precision)
    sgemm_kernel<false,false><<<dim3(3*D_/64, T_/64, 1), 256>>>(
        p_h, w_qkv, b_qkv, nullptr, p_qkv, T_, 3*D_, D_);

    // attention
    attn_kernel<<<dim3(S_/64, H_, B_), 256>>>(p_qkv, p_attn);

    // out-proj + residual: x1 = x + attn @ w_out + b_out (fp32)
    sgemm_kernel<false,true><<<dim3(D_/64, T_/64, 1), 256>>>(
        p_attn, w_out, b_out, x, p_x1, T_, D_, D_);

    // LN2
    ln_kernel<<<T_, 256>>>(p_x1, ln2_g, ln2_b, p_moein);

    // gate + routing (fp32)
    gate_kernel<<<T_, 128>>>(p_moein, w_gate);

    // expert GEMM1 (tf32 mma): he = gelu(gather(moe_in) @ w1[e] + b1[e])
    moe_mma_kernel<true><<<dim3(DFF_/64, T_/128, E_), 256>>>(
        p_moein, w1, b1, p_he,
        DFF_, D_, p_exTok, p_exDst, p_cnt,
        (size_t)D_*DFF_, DFF_, T_);

    // expert GEMM2 (tf32 mma): ybuf = gather(he) @ w2[e] + b2[e]
    moe_mma_kernel<false><<<dim3(D_/64, T_/128, E_), 256>>>(
        p_he, w2, b2, p_ybuf,
        D_, DFF_, p_exDst, p_exDst, p_cnt,
        (size_t)DFF_*D_, D_, T_);

    // combine: out = x1 + w0*y0 + w1*y1
    combine_kernel<<<(T_*D_/4 + 255)/256, 256>>>(p_x1, out);
}

// round 3
// speedup vs baseline: 2.0690x; 1.2524x over previous
#include <cuda_runtime.h>
#include <math.h>

#define B_ 4
#define S_ 2048
#define D_ 1024
#define H_ 16
#define DH_ 64
#define E_ 8
#define DFF_ 4096
#define T_ (B_*S_)          // 8192 tokens

// ---------------- scratch (device globals; no cudaMalloc allowed) ----------
__device__ float g_h[(size_t)T_*D_];            // LN1 out
__device__ float g_qkv[(size_t)T_*3*D_];        // qkv
__device__ float g_attn[(size_t)T_*D_];         // attention out
__device__ float g_x1[(size_t)T_*D_];           // post-attn residual
__device__ float g_moein[(size_t)T_*D_];        // LN2 out
__device__ float g_he[(size_t)2*T_*DFF_];       // expert hidden
__device__ float g_ybuf[(size_t)2*T_*D_];       // expert out
__device__ int   g_cnt[E_];
__device__ int   g_exTok[E_*T_];
__device__ int   g_exDst[E_*T_];
__device__ float g_tokW[2*T_];

// smem geometry shared by both mma kernels (floats)
#define AS_SZ (128*36)
#define BS_SZ (32*136)
#define STG_SZ (AS_SZ + BS_SZ)
#define DSMEM_BYTES (2*STG_SZ*4)      // 71680 B

__device__ __forceinline__ unsigned f2tf32(float x) {
    unsigned r;
    asm("cvt.rna.tf32.f32 %0, %1;" : "=r"(r) : "f"(x));
    return r;
}
__device__ __forceinline__ void cpasync16(float* dst, const float* src, bool pred) {
    unsigned d = (unsigned)__cvta_generic_to_shared(dst);
    int sz = pred ? 16 : 0;
    asm volatile("cp.async.cg.shared.global [%0], [%1], 16, %2;\n"
                 :: "r"(d), "l"(src), "r"(sz));
}
#define MMA_TF32(c, a0,a1,a2,a3, b0,b1)                                     \
    asm volatile(                                                           \
        "mma.sync.aligned.m16n8k8.row.col.f32.tf32.tf32.f32 "               \
        "{%0,%1,%2,%3}, {%4,%5,%6,%7}, {%8,%9}, {%0,%1,%2,%3};\n"           \
        : "+f"((c)[0]), "+f"((c)[1]), "+f"((c)[2]), "+f"((c)[3])            \
        : "r"(a0), "r"(a1), "r"(a2), "r"(a3), "r"(b0), "r"(b1))

// ---------------------------------------------------------------- zero cnt
__global__ void zero_cnt_kernel() {
    if (threadIdx.x < E_) g_cnt[threadIdx.x] = 0;
}

// ---------------------------------------------------------------- layernorm
__global__ void ln_kernel(const float* __restrict__ x,
                          const float* __restrict__ g,
                          const float* __restrict__ b,
                          float* __restrict__ out) {
    int row = blockIdx.x;
    int t = threadIdx.x;                       // 256 threads
    const float* xr = x + (size_t)row * D_;
    float v[4];
    float s = 0.f, ss = 0.f;
#pragma unroll
    for (int i = 0; i < 4; i++) {
        v[i] = xr[t + i*256];
        s += v[i]; ss += v[i]*v[i];
    }
#pragma unroll
    for (int m = 16; m; m >>= 1) {
        s  += __shfl_xor_sync(~0u, s, m);
        ss += __shfl_xor_sync(~0u, ss, m);
    }
    __shared__ float rs[8], rss[8];
    if ((t & 31) == 0) { rs[t>>5] = s; rss[t>>5] = ss; }
    __syncthreads();
    float sum = 0.f, sumsq = 0.f;
#pragma unroll
    for (int i = 0; i < 8; i++) { sum += rs[i]; sumsq += rss[i]; }
    float mean = sum * (1.f/D_);
    float var  = sumsq * (1.f/D_) - mean*mean;
    float rstd = rsqrtf(var + 1e-5f);
    float* orow = out + (size_t)row * D_;
#pragma unroll
    for (int i = 0; i < 4; i++) {
        int c = t + i*256;
        orow[c] = (v[i]-mean)*rstd*g[c] + b[c];
    }
}

// ---------------------------------------------------------------- MoE mma v2
// C[scatter(m),n] = act(gather(A) @ B_e + bias_e); raw tf32 operands.
// 128x128x32 block, 8 warps (2M x 4N), warp tile 64x32, cp.async 2-stage.
template<bool GELU>
__global__ void __launch_bounds__(256, 2)
moe_mma_kernel(const float* __restrict__ A,
               const float* __restrict__ Bw,
               const float* __restrict__ bias,
               float* __restrict__ C,
               int N, int K,
               const int* __restrict__ gatherA,
               const int* __restrict__ scatterC,
               const int* __restrict__ cnt,
               size_t bStride, int biasStride, int listStride)
{
    extern __shared__ float smem[];
    int e = blockIdx.z;
    int Me = cnt[e];
    int m0 = blockIdx.y * 128;
    if (m0 >= Me) return;
    int n0 = blockIdx.x * 128;

    const float* Bp    = Bw + (size_t)e * bStride;
    const float* biasp = bias + (size_t)e * biasStride;
    const int*   gA    = gatherA  + (size_t)e * listStride;
    const int*   sC    = scatterC + (size_t)e * listStride;

    int tid = threadIdx.x, lane = tid & 31, warp = tid >> 5;
    int wm = warp >> 2, wn = warp & 3;       // warp tile: M 64 @ wm, N 32 @ wn
    int fr = lane >> 2, fc = lane & 3;

    // ---- cp.async source setup ----
    int aRowBase = tid >> 3;           // +i*32
    int aKq = (tid & 7) * 4;
    const float* aSrc[4]; bool aValid[4];
#pragma unroll
    for (int i = 0; i < 4; i++) {
        int r = aRowBase + i*32;
        int rowA = m0 + r;
        aValid[i] = rowA < Me;
        aSrc[i] = aValid[i] ? (A + (size_t)gA[rowA]*K + aKq) : A;
    }
    int bKBase = tid >> 5;             // +i*8
    int bn4 = (tid & 31) * 4;
    const float* bSrc[4];
#pragma unroll
    for (int i = 0; i < 4; i++)
        bSrc[i] = Bp + (size_t)(bKBase + i*8)*N + n0 + bn4;

    float acc[4][4][4];
#pragma unroll
    for (int mi = 0; mi < 4; mi++)
#pragma unroll
        for (int ni = 0; ni < 4; ni++)
#pragma unroll
            for (int j = 0; j < 4; j++) acc[mi][ni][j] = 0.f;

    int nk = K >> 5;

    auto prefetch = [&](int s, int kt) {
        float* As_ = smem + s*STG_SZ;
        float* Bs_ = As_ + AS_SZ;
#pragma unroll
        for (int i = 0; i < 4; i++)
            cpasync16(As_ + (aRowBase + i*32)*36 + aKq,
                      aSrc[i] + (size_t)kt*32, aValid[i]);
#pragma unroll
        for (int i = 0; i < 4; i++)
            cpasync16(Bs_ + (bKBase + i*8)*136 + bn4,
                      bSrc[i] + (size_t)kt*32*N, true);
        asm volatile("cp.async.commit_group;\n");
    };

    prefetch(0, 0);

    for (int kt = 0; kt < nk; kt++) {
        int s = kt & 1;
        bool more = (kt + 1) < nk;
        if (more) prefetch(s ^ 1, kt + 1);
        if (more) asm volatile("cp.async.wait_group 1;\n");
        else      asm volatile("cp.async.wait_group 0;\n");
        __syncthreads();

        const float* As_ = smem + s*STG_SZ;
        const float* Bs_ = As_ + AS_SZ;
#pragma unroll
        for (int kk8 = 0; kk8 < 4; kk8++) {
            int kk = kk8 * 8;
            unsigned af[4][4], bf[4][2];
#pragma unroll
            for (int mi = 0; mi < 4; mi++) {
                int mb = wm*64 + mi*16;
                af[mi][0] = __float_as_uint(As_[(mb + fr    )*36 + kk + fc    ]);
                af[mi][1] = __float_as_uint(As_[(mb + fr + 8)*36 + kk + fc    ]);
                af[mi][2] = __float_as_uint(As_[(mb + fr    )*36 + kk + fc + 4]);
                af[mi][3] = __float_as_uint(As_[(mb + fr + 8)*36 + kk + fc + 4]);
            }
#pragma unroll
            for (int ni = 0; ni < 4; ni++) {
                int cb = wn*32 + ni*8;
                bf[ni][0] = __float_as_uint(Bs_[(kk + fc    )*136 + cb + fr]);
                bf[ni][1] = __float_as_uint(Bs_[(kk + fc + 4)*136 + cb + fr]);
            }
#pragma unroll
            for (int mi = 0; mi < 4; mi++)
#pragma unroll
                for (int ni = 0; ni < 4; ni++)
                    MMA_TF32(acc[mi][ni], af[mi][0],af[mi][1],af[mi][2],af[mi][3],
                             bf[ni][0], bf[ni][1]);
        }
        __syncthreads();
    }

    // ---- epilogue: bias (+gelu), scatter rows ----
#pragma unroll
    for (int mi = 0; mi < 4; mi++) {
        int rbase = m0 + wm*64 + mi*16 + fr;
#pragma unroll
        for (int half = 0; half < 2; half++) {
            int m = rbase + half*8;
            if (m >= Me) continue;
            int crow = sC[m];
#pragma unroll
            for (int ni = 0; ni < 4; ni++) {
                int n = n0 + wn*32 + ni*8 + fc*2;
                float v0 = acc[mi][ni][half*2 + 0] + biasp[n];
                float v1 = acc[mi][ni][half*2 + 1] + biasp[n+1];
                if (GELU) {
                    float u = v0;
                    v0 = 0.5f*u*(1.f + tanhf(0.7978845608028654f*(u + 0.044715f*u*u*u)));
                    u = v1;
                    v1 = 0.5f*u*(1.f + tanhf(0.7978845608028654f*(u + 0.044715f*u*u*u)));
                }
                *(float2*)(C + (size_t)crow * N + n) = make_float2(v0, v1);
            }
        }
    }
}

// ---------------------------------------------------------------- 3xTF32 dense GEMM
// fp32-accurate GEMM via hi/lo tf32 split (drops lo*lo): err ~2^-22.
// 128x128x32 block, 8 warps (2M x 4N), register double-buffered loads.
template<bool RES>
__global__ void __launch_bounds__(256, 1)
mma3_kernel(const float* __restrict__ A,
            const float* __restrict__ Bw,
            const float* __restrict__ bias,
            const float* __restrict__ res,
            float* __restrict__ C,
            int N, int K)
{
    extern __shared__ float smem[];
    float* As_hi = smem;
    float* As_lo = smem + AS_SZ;
    float* Bs_hi = smem + 2*AS_SZ;
    float* Bs_lo = smem + 2*AS_SZ + BS_SZ;

    int m0 = blockIdx.y * 128;
    int n0 = blockIdx.x * 128;

    int tid = threadIdx.x, lane = tid & 31, warp = tid >> 5;
    int wm = warp >> 2, wn = warp & 3;
    int fr = lane >> 2, fc = lane & 3;

    int aRowBase = tid >> 3;
    int aKq = (tid & 7) * 4;
    const float* aSrc[4];
#pragma unroll
    for (int i = 0; i < 4; i++)
        aSrc[i] = A + (size_t)(m0 + aRowBase + i*32)*K + aKq;
    int bKBase = tid >> 5;
    int bn4 = (tid & 31) * 4;
    const float* bSrc[4];
#pragma unroll
    for (int i = 0; i < 4; i++)
        bSrc[i] = Bw + (size_t)(bKBase + i*8)*N + n0 + bn4;

    float4 pa[4], pb[4];
#define LOADG3(k0)                                                        \
    {                                                                     \
        _Pragma("unroll")                                                 \
        for (int i = 0; i < 4; i++)                                       \
            pa[i] = *(const float4*)(aSrc[i] + (k0));                     \
        _Pragma("unroll")                                                 \
        for (int i = 0; i < 4; i++)                                       \
            pb[i] = *(const float4*)(bSrc[i] + (size_t)(k0)*N);           \
    }
#define SPLIT4(dhi, dlo, v)                                               \
    {                                                                     \
        float src4[4] = {(v).x, (v).y, (v).z, (v).w};                     \
        float h4[4], l4[4];                                               \
        _Pragma("unroll")                                                 \
        for (int q = 0; q < 4; q++) {                                     \
            float hf = __uint_as_float(f2tf32(src4[q]));                  \
            h4[q] = hf;                                                   \
            l4[q] = __uint_as_float(f2tf32(src4[q] - hf));                \
        }                                                                 \
        *(float4*)(dhi) = make_float4(h4[0], h4[1], h4[2], h4[3]);        \
        *(float4*)(dlo) = make_float4(l4[0], l4[1], l4[2], l4[3]);        \
    }
#define STORES3()                                                         \
    {                                                                     \
        _Pragma("unroll")                                                 \
        for (int i = 0; i < 4; i++) {                                     \
            int off = (aRowBase + i*32)*36 + aKq;                         \
            SPLIT4(As_hi + off, As_lo + off, pa[i]);                      \
        }                                                                 \
        _Pragma("unroll")                                                 \
        for (int i = 0; i < 4; i++) {                                     \
            int off = (bKBase + i*8)*136 + bn4;                           \
            SPLIT4(Bs_hi + off, Bs_lo + off, pb[i]);                      \
        }                                                                 \
    }

    float acc[4][4][4];
#pragma unroll
    for (int mi = 0; mi < 4; mi++)
#pragma unroll
        for (int ni = 0; ni < 4; ni++)
#pragma unroll
            for (int j = 0; j < 4; j++) acc[mi][ni][j] = 0.f;

    LOADG3(0);
    STORES3();
    __syncthreads();

    for (int k0 = 0; k0 < K; k0 += 32) {
        bool more = (k0 + 32) < K;
        if (more) LOADG3(k0 + 32);

#pragma unroll
        for (int kk8 = 0; kk8 < 4; kk8++) {
            int kk = kk8 * 8;
            unsigned ah[4][4], al[4][4], bh[4][2], bl[4][2];
#pragma unroll
            for (int mi = 0; mi < 4; mi++) {
                int mb = wm*64 + mi*16;
                int o0 = (mb + fr    )*36 + kk + fc;
                int o1 = (mb + fr + 8)*36 + kk + fc;
                ah[mi][0] = __float_as_uint(As_hi[o0]);
                ah[mi][1] = __float_as_uint(As_hi[o1]);
                ah[mi][2] = __float_as_uint(As_hi[o0 + 4]);
                ah[mi][3] = __float_as_uint(As_hi[o1 + 4]);
                al[mi][0] = __float_as_uint(As_lo[o0]);
                al[mi][1] = __float_as_uint(As_lo[o1]);
                al[mi][2] = __float_as_uint(As_lo[o0 + 4]);
                al[mi][3] = __float_as_uint(As_lo[o1 + 4]);
            }
#pragma unroll
            for (int ni = 0; ni < 4; ni++) {
                int cb = wn*32 + ni*8;
                int o0 = (kk + fc    )*136 + cb + fr;
                int o1 = (kk + fc + 4)*136 + cb + fr;
                bh[ni][0] = __float_as_uint(Bs_hi[o0]);
                bh[ni][1] = __float_as_uint(Bs_hi[o1]);
                bl[ni][0] = __float_as_uint(Bs_lo[o0]);
                bl[ni][1] = __float_as_uint(Bs_lo[o1]);
            }
#pragma unroll
            for (int mi = 0; mi < 4; mi++)
#pragma unroll
                for (int ni = 0; ni < 4; ni++) {
                    MMA_TF32(acc[mi][ni], ah[mi][0],ah[mi][1],ah[mi][2],ah[mi][3],
                             bl[ni][0], bl[ni][1]);
                    MMA_TF32(acc[mi][ni], al[mi][0],al[mi][1],al[mi][2],al[mi][3],
                             bh[ni][0], bh[ni][1]);
                    MMA_TF32(acc[mi][ni], ah[mi][0],ah[mi][1],ah[mi][2],ah[mi][3],
                             bh[ni][0], bh[ni][1]);
                }
        }
        __syncthreads();
        if (more) {
            STORES3();
            __syncthreads();
        }
    }

    // ---- epilogue ----
#pragma unroll
    for (int mi = 0; mi < 4; mi++) {
        int rbase = m0 + wm*64 + mi*16 + fr;
#pragma unroll
        for (int half = 0; half < 2; half++) {
            int m = rbase + half*8;
#pragma unroll
            for (int ni = 0; ni < 4; ni++) {
                int n = n0 + wn*32 + ni*8 + fc*2;
                float v0 = acc[mi][ni][half*2 + 0] + bias[n];
                float v1 = acc[mi][ni][half*2 + 1] + bias[n+1];
                if (RES) {
                    v0 += res[(size_t)m * N + n];
                    v1 += res[(size_t)m * N + n + 1];
                }
                *(float2*)(C + (size_t)m * N + n) = make_float2(v0, v1);
            }
        }
    }
#undef LOADG3
#undef SPLIT4
#undef STORES3
}

// ---------------------------------------------------------------- attention
__global__ void attn_kernel(const float* __restrict__ qkv, float* __restrict__ o)
{
    __shared__ __align__(16) float QT[64*64];   // [d][q], pre-scaled
    __shared__ __align__(16) float KT[64*64];   // [d][k], reused for P[k][q]
    __shared__ __align__(16) float Vs[64*64];   // [k][d]

    int qt = blockIdx.x, h = blockIdx.y, b = blockIdx.z;
    int tid = threadIdx.x;
    int tx = tid & 15, ty = tid >> 4;
    size_t base = (size_t)b * S_ * (3*D_);

#pragma unroll
    for (int rep = 0; rep < 4; rep++) {
        int idx = rep*1024 + tid*4;
        int r = idx >> 6, d0 = idx & 63;
        const float* p = qkv + base + (size_t)(qt*64 + r)*(3*D_) + h*DH_ + d0;
        float4 q = *(const float4*)p;
        QT[(d0+0)*64 + r] = q.x * 0.125f;
        QT[(d0+1)*64 + r] = q.y * 0.125f;
        QT[(d0+2)*64 + r] = q.z * 0.125f;
        QT[(d0+3)*64 + r] = q.w * 0.125f;
    }

    float m_[4], l_[4], oacc[4][4];
#pragma unroll
    for (int i = 0; i < 4; i++) {
        m_[i] = -1e30f; l_[i] = 0.f;
#pragma unroll
        for (int j = 0; j < 4; j++) oacc[i][j] = 0.f;
    }

    for (int kt = 0; kt < S_/64; kt++) {
#pragma unroll
        for (int rep = 0; rep < 4; rep++) {
            int idx = rep*1024 + tid*4;
            int r = idx >> 6, d0 = idx & 63;
            size_t rowoff = base + (size_t)(kt*64 + r)*(3*D_) + h*DH_ + d0;
            float4 kv = *(const float4*)(qkv + rowoff + D_);
            KT[(d0+0)*64 + r] = kv.x;
            KT[(d0+1)*64 + r] = kv.y;
            KT[(d0+2)*64 + r] = kv.z;
            KT[(d0+3)*64 + r] = kv.w;
            float4 vv = *(const float4*)(qkv + rowoff + 2*D_);
            *(float4*)(Vs + r*64 + d0) = vv;
        }
        __syncthreads();

        float s[4][4] = {};
#pragma unroll
        for (int kk = 0; kk < 64; kk++) {
            float4 a = *(const float4*)(QT + kk*64 + ty*4);
            float4 bb = *(const float4*)(KT + kk*64 + tx*4);
            float av[4] = {a.x,a.y,a.z,a.w};
            float bv[4] = {bb.x,bb.y,bb.z,bb.w};
#pragma unroll
            for (int i = 0; i < 4; i++)
#pragma unroll
                for (int j = 0; j < 4; j++)
                    s[i][j] = fmaf(av[i], bv[j], s[i][j]);
        }
        __syncthreads();

#pragma unroll
        for (int i = 0; i < 4; i++) {
            float rm = fmaxf(fmaxf(s[i][0], s[i][1]), fmaxf(s[i][2], s[i][3]));
#pragma unroll
            for (int msk = 1; msk < 16; msk <<= 1)
                rm = fmaxf(rm, __shfl_xor_sync(~0u, rm, msk));
            float mn = fmaxf(m_[i], rm);
            float alpha = __expf(m_[i] - mn);
            float rsum = 0.f;
#pragma unroll
            for (int j = 0; j < 4; j++) { s[i][j] = __expf(s[i][j] - mn); rsum += s[i][j]; }
#pragma unroll
            for (int msk = 1; msk < 16; msk <<= 1)
                rsum += __shfl_xor_sync(~0u, rsum, msk);
            l_[i] = l_[i]*alpha + rsum;
            m_[i] = mn;
#pragma unroll
            for (int j = 0; j < 4; j++) oacc[i][j] *= alpha;
        }
#pragma unroll
        for (int j = 0; j < 4; j++)
            *(float4*)(KT + (tx*4+j)*64 + ty*4) =
                make_float4(s[0][j], s[1][j], s[2][j], s[3][j]);
        __syncthreads();

#pragma unroll
        for (int c = 0; c < 64; c++) {
            float4 pv = *(const float4*)(KT + c*64 + ty*4);
            float4 vv = *(const float4*)(Vs + c*64 + tx*4);
            float pva[4] = {pv.x,pv.y,pv.z,pv.w};
            float vva[4] = {vv.x,vv.y,vv.z,vv.w};
#pragma unroll
            for (int i = 0; i < 4; i++)
#pragma unroll
                for (int j = 0; j < 4; j++)
                    oacc[i][j] = fmaf(pva[i], vva[j], oacc[i][j]);
        }
        __syncthreads();
    }

#pragma unroll
    for (int i = 0; i < 4; i++) {
        float inv = 1.f / l_[i];
        int tok = b*S_ + qt*64 + ty*4 + i;
        *(float4*)(o + (size_t)tok*D_ + h*DH_ + tx*4) =
            make_float4(oacc[i][0]*inv, oacc[i][1]*inv,
                        oacc[i][2]*inv, oacc[i][3]*inv);
    }
}

// ---------------------------------------------------------------- gate/top2
__global__ void gate_kernel(const float* __restrict__ xin,
                            const float* __restrict__ wg)
{
    int t = blockIdx.x;
    int tid = threadIdx.x;     // 128
    const float* xr = xin + (size_t)t * D_;
    float acc[E_] = {};
    for (int d = tid; d < D_; d += 128) {
        float xv = xr[d];
        const float* w = wg + d*E_;
#pragma unroll
        for (int e = 0; e < E_; e++) acc[e] = fmaf(xv, w[e], acc[e]);
    }
#pragma unroll
    for (int e = 0; e < E_; e++)
#pragma unroll
        for (int msk = 16; msk; msk >>= 1)
            acc[e] += __shfl_xor_sync(~0u, acc[e], msk);
    __shared__ float red[4][E_];
    if ((tid & 31) == 0)
#pragma unroll
        for (int e = 0; e < E_; e++) red[tid>>5][e] = acc[e];
    __syncthreads();
    if (tid == 0) {
        float lg[E_];
#pragma unroll
        for (int e = 0; e < E_; e++)
            lg[e] = red[0][e] + red[1][e] + red[2][e] + red[3][e];
        int i0 = 0;
#pragma unroll
        for (int e = 1; e < E_; e++) if (lg[e] > lg[i0]) i0 = e;
        int i1 = -1;
#pragma unroll
        for (int e = 0; e < E_; e++)
            if (e != i0 && (i1 < 0 || lg[e] > lg[i1])) i1 = e;
        float d10 = __expf(lg[i1] - lg[i0]);        // <= 1
        float w0 = 1.f / (1.f + d10);
        float w1 = d10 * w0;
        g_tokW[2*t]   = w0;
        g_tokW[2*t+1] = w1;
        int p0 = atomicAdd(&g_cnt[i0], 1);
        g_exTok[i0*T_ + p0] = t;  g_exDst[i0*T_ + p0] = 2*t;
        int p1 = atomicAdd(&g_cnt[i1], 1);
        g_exTok[i1*T_ + p1] = t;  g_exDst[i1*T_ + p1] = 2*t+1;
    }
}

// ---------------------------------------------------------------- combine
__global__ void combine_kernel(const float* __restrict__ x1,
                               float* __restrict__ out)
{
    size_t idx = ((size_t)blockIdx.x * 256 + threadIdx.x) * 4;
    if (idx >= (size_t)T_*D_) return;
    int t = (int)(idx >> 10);
    int c = (int)(idx & (D_-1));
    float w0 = g_tokW[2*t], w1 = g_tokW[2*t+1];
    float4 a  = *(const float4*)(x1 + idx);
    float4 y0 = *(const float4*)(g_ybuf + (size_t)(2*t)*D_ + c);
    float4 y1 = *(const float4*)(g_ybuf + (size_t)(2*t+1)*D_ + c);
    float4 r;
    r.x = a.x + w0*y0.x + w1*y1.x;
    r.y = a.y + w0*y0.y + w1*y1.y;
    r.z = a.z + w0*y0.z + w1*y1.z;
    r.w = a.w + w0*y0.w + w1*y1.w;
    *(float4*)(out + idx) = r;
}

// ---------------------------------------------------------------- launch
extern "C" void kernel_launch(void* const* d_in, const int* in_sizes, int n_in,
                              void* d_out, int out_size)
{
    const float* x      = (const float*)d_in[0];
    const float* ln1_g  = (const float*)d_in[1];
    const float* ln1_b  = (const float*)d_in[2];
    const float* ln2_g  = (const float*)d_in[3];
    const float* ln2_b  = (const float*)d_in[4];
    const float* w_qkv  = (const float*)d_in[5];
    const float* b_qkv  = (const float*)d_in[6];
    const float* w_out  = (const float*)d_in[7];
    const float* b_out  = (const float*)d_in[8];
    const float* w_gate = (const float*)d_in[9];
    const float* w1     = (const float*)d_in[10];
    const float* b1     = (const float*)d_in[11];
    const float* w2     = (const float*)d_in[12];
    const float* b2     = (const float*)d_in[13];
    float* out = (float*)d_out;

    float *p_h, *p_qkv, *p_attn, *p_x1, *p_moein, *p_he, *p_ybuf;
    int *p_exTok, *p_exDst, *p_cnt;
    cudaGetSymbolAddress((void**)&p_h,     g_h);
    cudaGetSymbolAddress((void**)&p_qkv,   g_qkv);
    cudaGetSymbolAddress((void**)&p_attn,  g_attn);
    cudaGetSymbolAddress((void**)&p_x1,    g_x1);
    cudaGetSymbolAddress((void**)&p_moein, g_moein);
    cudaGetSymbolAddress((void**)&p_he,    g_he);
    cudaGetSymbolAddress((void**)&p_ybuf,  g_ybuf);
    cudaGetSymbolAddress((void**)&p_exTok, g_exTok);
    cudaGetSymbolAddress((void**)&p_exDst, g_exDst);
    cudaGetSymbolAddress((void**)&p_cnt,   g_cnt);

    static int attrDone = 0;
    if (!attrDone) {
        cudaFuncSetAttribute(moe_mma_kernel<true>,
            cudaFuncAttributeMaxDynamicSharedMemorySize, DSMEM_BYTES);
        cudaFuncSetAttribute(moe_mma_kernel<false>,
            cudaFuncAttributeMaxDynamicSharedMemorySize, DSMEM_BYTES);
        cudaFuncSetAttribute(mma3_kernel<false>,
            cudaFuncAttributeMaxDynamicSharedMemorySize, DSMEM_BYTES);
        cudaFuncSetAttribute(mma3_kernel<true>,
            cudaFuncAttributeMaxDynamicSharedMemorySize, DSMEM_BYTES);
        attrDone = 1;
    }

    zero_cnt_kernel<<<1, 32>>>();

    // LN1
    ln_kernel<<<T_, 256>>>(x, ln1_g, ln1_b, p_h);

    // QKV (3xTF32, fp32-grade): qkv = h @ w_qkv + b_qkv
    mma3_kernel<false><<<dim3(3*D_/128, T_/128, 1), 256, DSMEM_BYTES>>>(
        p_h, w_qkv, b_qkv, nullptr, p_qkv, 3*D_, D_);

    // attention (fp32)
    attn_kernel<<<dim3(S_/64, H_, B_), 256>>>(p_qkv, p_attn);

    // out-proj + residual (3xTF32): x1 = x + attn @ w_out + b_out
    mma3_kernel<true><<<dim3(D_/128, T_/128, 1), 256, DSMEM_BYTES>>>(
        p_attn, w_out, b_out, x, p_x1, D_, D_);

    // LN2
    ln_kernel<<<T_, 256>>>(p_x1, ln2_g, ln2_b, p_moein);

    // gate + routing (fp32)
    gate_kernel<<<T_, 128>>>(p_moein, w_gate);

    // expert GEMM1 (tf32 mma): he = gelu(gather(moe_in) @ w1[e] + b1[e])
    moe_mma_kernel<true><<<dim3(DFF_/128, T_/128, E_), 256, DSMEM_BYTES>>>(
        p_moein, w1, b1, p_he,
        DFF_, D_, p_exTok, p_exDst, p_cnt,
        (size_t)D_*DFF_, DFF_, T_);

    // expert GEMM2 (tf32 mma): ybuf = gather(he) @ w2[e] + b2[e]
    moe_mma_kernel<false><<<dim3(D_/128, T_/128, E_), 256, DSMEM_BYTES>>>(
        p_he, w2, b2, p_ybuf,
        D_, DFF_, p_exDst, p_exDst, p_cnt,
        (size_t)DFF_*D_, D_, T_);

    // combine: out = x1 + w0*y0 + w1*y1
    combine_kernel<<<(T_*D_/4 + 255)/256, 256>>>(p_x1, out);
}

// round 4
// speedup vs baseline: 2.5153x; 1.2157x over previous
#include <cuda_runtime.h>
#include <math.h>

#define B_ 4
#define S_ 2048
#define D_ 1024
#define H_ 16
#define DH_ 64
#define E_ 8
#define DFF_ 4096
#define T_ (B_*S_)          // 8192 tokens

// ---------------- scratch (device globals; no cudaMalloc allowed) ----------
__device__ float g_h[(size_t)T_*D_];            // LN1 out
__device__ float g_qkv[(size_t)T_*3*D_];        // qkv
__device__ float g_attn[(size_t)T_*D_];         // attention out
__device__ float g_x1[(size_t)T_*D_];           // post-attn residual
__device__ float g_moein[(size_t)T_*D_];        // LN2 out
__device__ float g_he[(size_t)2*T_*DFF_];       // expert hidden
__device__ float g_ybuf[(size_t)2*T_*D_];       // expert out
__device__ float g_w1r[(size_t)E_*D_*DFF_];     // RNA-rounded w1
__device__ float g_w2r[(size_t)E_*DFF_*D_];     // RNA-rounded w2
__device__ int   g_cnt[E_];
__device__ int   g_exTok[E_*T_];
__device__ int   g_exDst[E_*T_];
__device__ float g_tokW[2*T_];

// smem geometry shared by mma GEMM kernels (floats)
#define AS_SZ (128*36)
#define BS_SZ (32*136)
#define STG_SZ (AS_SZ + BS_SZ)
#define DSMEM_BYTES (2*STG_SZ*4)      // 71680 B
#define ATTN_SMEM (2*64*68*8)         // 2 float2 buffers [64][68] = 69632 B

__device__ __forceinline__ unsigned f2tf32(float x) {
    unsigned r;
    asm("cvt.rna.tf32.f32 %0, %1;" : "=r"(r) : "f"(x));
    return r;
}
__device__ __forceinline__ float rndtf32(float x) {
    return __uint_as_float(f2tf32(x));
}
__device__ __forceinline__ void cpasync16(float* dst, const float* src, bool pred) {
    unsigned d = (unsigned)__cvta_generic_to_shared(dst);
    int sz = pred ? 16 : 0;
    asm volatile("cp.async.cg.shared.global [%0], [%1], 16, %2;\n"
                 :: "r"(d), "l"(src), "r"(sz));
}
#define MMA_TF32(c, a0,a1,a2,a3, b0,b1)                                     \
    asm volatile(                                                           \
        "mma.sync.aligned.m16n8k8.row.col.f32.tf32.tf32.f32 "               \
        "{%0,%1,%2,%3}, {%4,%5,%6,%7}, {%8,%9}, {%0,%1,%2,%3};\n"           \
        : "+f"((c)[0]), "+f"((c)[1]), "+f"((c)[2]), "+f"((c)[3])            \
        : "r"(a0), "r"(a1), "r"(a2), "r"(a3), "r"(b0), "r"(b1))

// ---------------------------------------------------------------- zero cnt
__global__ void zero_cnt_kernel() {
    if (threadIdx.x < E_) g_cnt[threadIdx.x] = 0;
}

// ---------------------------------------------------------------- RNA round (copy or in-place)
__global__ void round_kernel(const float* __restrict__ in,
                             float* __restrict__ out, int n4) {
    int i = blockIdx.x * 256 + threadIdx.x;
    if (i >= n4) return;
    float4 v = *(const float4*)(in + (size_t)i*4);
    v.x = rndtf32(v.x); v.y = rndtf32(v.y);
    v.z = rndtf32(v.z); v.w = rndtf32(v.w);
    *(float4*)(out + (size_t)i*4) = v;
}

// ---------------------------------------------------------------- layernorm
__global__ void ln_kernel(const float* __restrict__ x,
                          const float* __restrict__ g,
                          const float* __restrict__ b,
                          float* __restrict__ out) {
    int row = blockIdx.x;
    int t = threadIdx.x;                       // 256 threads
    const float* xr = x + (size_t)row * D_;
    float v[4];
    float s = 0.f, ss = 0.f;
#pragma unroll
    for (int i = 0; i < 4; i++) {
        v[i] = xr[t + i*256];
        s += v[i]; ss += v[i]*v[i];
    }
#pragma unroll
    for (int m = 16; m; m >>= 1) {
        s  += __shfl_xor_sync(~0u, s, m);
        ss += __shfl_xor_sync(~0u, ss, m);
    }
    __shared__ float rs[8], rss[8];
    if ((t & 31) == 0) { rs[t>>5] = s; rss[t>>5] = ss; }
    __syncthreads();
    float sum = 0.f, sumsq = 0.f;
#pragma unroll
    for (int i = 0; i < 8; i++) { sum += rs[i]; sumsq += rss[i]; }
    float mean = sum * (1.f/D_);
    float var  = sumsq * (1.f/D_) - mean*mean;
    float rstd = rsqrtf(var + 1e-5f);
    float* orow = out + (size_t)row * D_;
#pragma unroll
    for (int i = 0; i < 4; i++) {
        int c = t + i*256;
        orow[c] = (v[i]-mean)*rstd*g[c] + b[c];
    }
}

// ---------------------------------------------------------------- MoE mma
// C[scatter(m),n] = act(gather(A) @ B_e + bias_e); operands pre-rounded RNA tf32.
// 128x128x32 block, 8 warps (2M x 4N), cp.async 2-stage.
template<bool GELU>
__global__ void __launch_bounds__(256, 2)
moe_mma_kernel(const float* __restrict__ A,
               const float* __restrict__ Bw,
               const float* __restrict__ bias,
               float* __restrict__ C,
               int N, int K,
               const int* __restrict__ gatherA,
               const int* __restrict__ scatterC,
               const int* __restrict__ cnt,
               size_t bStride, int biasStride, int listStride)
{
    extern __shared__ float smem[];
    int e = blockIdx.z;
    int Me = cnt[e];
    int m0 = blockIdx.y * 128;
    if (m0 >= Me) return;
    int n0 = blockIdx.x * 128;

    const float* Bp    = Bw + (size_t)e * bStride;
    const float* biasp = bias + (size_t)e * biasStride;
    const int*   gA    = gatherA  + (size_t)e * listStride;
    const int*   sC    = scatterC + (size_t)e * listStride;

    int tid = threadIdx.x, lane = tid & 31, warp = tid >> 5;
    int wm = warp >> 2, wn = warp & 3;
    int fr = lane >> 2, fc = lane & 3;

    int aRowBase = tid >> 3;           // +i*32
    int aKq = (tid & 7) * 4;
    const float* aSrc[4]; bool aValid[4];
#pragma unroll
    for (int i = 0; i < 4; i++) {
        int r = aRowBase + i*32;
        int rowA = m0 + r;
        aValid[i] = rowA < Me;
        aSrc[i] = aValid[i] ? (A + (size_t)gA[rowA]*K + aKq) : A;
    }
    int bKBase = tid >> 5;             // +i*8
    int bn4 = (tid & 31) * 4;
    const float* bSrc[4];
#pragma unroll
    for (int i = 0; i < 4; i++)
        bSrc[i] = Bp + (size_t)(bKBase + i*8)*N + n0 + bn4;

    float acc[4][4][4];
#pragma unroll
    for (int mi = 0; mi < 4; mi++)
#pragma unroll
        for (int ni = 0; ni < 4; ni++)
#pragma unroll
            for (int j = 0; j < 4; j++) acc[mi][ni][j] = 0.f;

    int nk = K >> 5;

    auto prefetch = [&](int s, int kt) {
        float* As_ = smem + s*STG_SZ;
        float* Bs_ = As_ + AS_SZ;
#pragma unroll
        for (int i = 0; i < 4; i++)
            cpasync16(As_ + (aRowBase + i*32)*36 + aKq,
                      aSrc[i] + (size_t)kt*32, aValid[i]);
#pragma unroll
        for (int i = 0; i < 4; i++)
            cpasync16(Bs_ + (bKBase + i*8)*136 + bn4,
                      bSrc[i] + (size_t)kt*32*N, true);
        asm volatile("cp.async.commit_group;\n");
    };

    prefetch(0, 0);

    for (int kt = 0; kt < nk; kt++) {
        int s = kt & 1;
        bool more = (kt + 1) < nk;
        if (more) prefetch(s ^ 1, kt + 1);
        if (more) asm volatile("cp.async.wait_group 1;\n");
        else      asm volatile("cp.async.wait_group 0;\n");
        __syncthreads();

        const float* As_ = smem + s*STG_SZ;
        const float* Bs_ = As_ + AS_SZ;
#pragma unroll
        for (int kk8 = 0; kk8 < 4; kk8++) {
            int kk = kk8 * 8;
            unsigned af[4][4], bf[4][2];
#pragma unroll
            for (int mi = 0; mi < 4; mi++) {
                int mb = wm*64 + mi*16;
                af[mi][0] = __float_as_uint(As_[(mb + fr    )*36 + kk + fc    ]);
                af[mi][1] = __float_as_uint(As_[(mb + fr + 8)*36 + kk + fc    ]);
                af[mi][2] = __float_as_uint(As_[(mb + fr    )*36 + kk + fc + 4]);
                af[mi][3] = __float_as_uint(As_[(mb + fr + 8)*36 + kk + fc + 4]);
            }
#pragma unroll
            for (int ni = 0; ni < 4; ni++) {
                int cb = wn*32 + ni*8;
                bf[ni][0] = __float_as_uint(Bs_[(kk + fc    )*136 + cb + fr]);
                bf[ni][1] = __float_as_uint(Bs_[(kk + fc + 4)*136 + cb + fr]);
            }
#pragma unroll
            for (int mi = 0; mi < 4; mi++)
#pragma unroll
                for (int ni = 0; ni < 4; ni++)
                    MMA_TF32(acc[mi][ni], af[mi][0],af[mi][1],af[mi][2],af[mi][3],
                             bf[ni][0], bf[ni][1]);
        }
        __syncthreads();
    }

#pragma unroll
    for (int mi = 0; mi < 4; mi++) {
        int rbase = m0 + wm*64 + mi*16 + fr;
#pragma unroll
        for (int half = 0; half < 2; half++) {
            int m = rbase + half*8;
            if (m >= Me) continue;
            int crow = sC[m];
#pragma unroll
            for (int ni = 0; ni < 4; ni++) {
                int n = n0 + wn*32 + ni*8 + fc*2;
                float v0 = acc[mi][ni][half*2 + 0] + biasp[n];
                float v1 = acc[mi][ni][half*2 + 1] + biasp[n+1];
                if (GELU) {
                    float u = v0;
                    v0 = 0.5f*u*(1.f + tanhf(0.7978845608028654f*(u + 0.044715f*u*u*u)));
                    u = v1;
                    v1 = 0.5f*u*(1.f + tanhf(0.7978845608028654f*(u + 0.044715f*u*u*u)));
                    v0 = rndtf32(v0);        // he is GEMM2's A operand: pre-round
                    v1 = rndtf32(v1);
                }
                *(float2*)(C + (size_t)crow * N + n) = make_float2(v0, v1);
            }
        }
    }
}

// ---------------------------------------------------------------- 3xTF32 dense GEMM
template<bool RES>
__global__ void __launch_bounds__(256, 1)
mma3_kernel(const float* __restrict__ A,
            const float* __restrict__ Bw,
            const float* __restrict__ bias,
            const float* __restrict__ res,
            float* __restrict__ C,
            int N, int K)
{
    extern __shared__ float smem[];
    float* As_hi = smem;
    float* As_lo = smem + AS_SZ;
    float* Bs_hi = smem + 2*AS_SZ;
    float* Bs_lo = smem + 2*AS_SZ + BS_SZ;

    int m0 = blockIdx.y * 128;
    int n0 = blockIdx.x * 128;

    int tid = threadIdx.x, lane = tid & 31, warp = tid >> 5;
    int wm = warp >> 2, wn = warp & 3;
    int fr = lane >> 2, fc = lane & 3;

    int aRowBase = tid >> 3;
    int aKq = (tid & 7) * 4;
    const float* aSrc[4];
#pragma unroll
    for (int i = 0; i < 4; i++)
        aSrc[i] = A + (size_t)(m0 + aRowBase + i*32)*K + aKq;
    int bKBase = tid >> 5;
    int bn4 = (tid & 31) * 4;
    const float* bSrc[4];
#pragma unroll
    for (int i = 0; i < 4; i++)
        bSrc[i] = Bw + (size_t)(bKBase + i*8)*N + n0 + bn4;

    float4 pa[4], pb[4];
#define LOADG3(k0)                                                        \
    {                                                                     \
        _Pragma("unroll")                                                 \
        for (int i = 0; i < 4; i++)                                       \
            pa[i] = *(const float4*)(aSrc[i] + (k0));                     \
        _Pragma("unroll")                                                 \
        for (int i = 0; i < 4; i++)                                       \
            pb[i] = *(const float4*)(bSrc[i] + (size_t)(k0)*N);           \
    }
#define SPLIT4(dhi, dlo, v)                                               \
    {                                                                     \
        float src4[4] = {(v).x, (v).y, (v).z, (v).w};                     \
        float h4[4], l4[4];                                               \
        _Pragma("unroll")                                                 \
        for (int q = 0; q < 4; q++) {                                     \
            float hf = rndtf32(src4[q]);                                  \
            h4[q] = hf;                                                   \
            l4[q] = rndtf32(src4[q] - hf);                                \
        }                                                                 \
        *(float4*)(dhi) = make_float4(h4[0], h4[1], h4[2], h4[3]);        \
        *(float4*)(dlo) = make_float4(l4[0], l4[1], l4[2], l4[3]);        \
    }
#define STORES3()                                                         \
    {                                                                     \
        _Pragma("unroll")                                                 \
        for (int i = 0; i < 4; i++) {                                     \
            int off = (aRowBase + i*32)*36 + aKq;                         \
            SPLIT4(As_hi + off, As_lo + off, pa[i]);                      \
        }                                                                 \
        _Pragma("unroll")                                                 \
        for (int i = 0; i < 4; i++) {                                     \
            int off = (bKBase + i*8)*136 + bn4;                           \
            SPLIT4(Bs_hi + off, Bs_lo + off, pb[i]);                      \
        }                                                                 \
    }

    float acc[4][4][4];
#pragma unroll
    for (int mi = 0; mi < 4; mi++)
#pragma unroll
        for (int ni = 0; ni < 4; ni++)
#pragma unroll
            for (int j = 0; j < 4; j++) acc[mi][ni][j] = 0.f;

    LOADG3(0);
    STORES3();
    __syncthreads();

    for (int k0 = 0; k0 < K; k0 += 32) {
        bool more = (k0 + 32) < K;
        if (more) LOADG3(k0 + 32);

#pragma unroll
        for (int kk8 = 0; kk8 < 4; kk8++) {
            int kk = kk8 * 8;
            unsigned ah[4][4], al[4][4], bh[4][2], bl[4][2];
#pragma unroll
            for (int mi = 0; mi < 4; mi++) {
                int mb = wm*64 + mi*16;
                int o0 = (mb + fr    )*36 + kk + fc;
                int o1 = (mb + fr + 8)*36 + kk + fc;
                ah[mi][0] = __float_as_uint(As_hi[o0]);
                ah[mi][1] = __float_as_uint(As_hi[o1]);
                ah[mi][2] = __float_as_uint(As_hi[o0 + 4]);
                ah[mi][3] = __float_as_uint(As_hi[o1 + 4]);
                al[mi][0] = __float_as_uint(As_lo[o0]);
                al[mi][1] = __float_as_uint(As_lo[o1]);
                al[mi][2] = __float_as_uint(As_lo[o0 + 4]);
                al[mi][3] = __float_as_uint(As_lo[o1 + 4]);
            }
#pragma unroll
            for (int ni = 0; ni < 4; ni++) {
                int cb = wn*32 + ni*8;
                int o0 = (kk + fc    )*136 + cb + fr;
                int o1 = (kk + fc + 4)*136 + cb + fr;
                bh[ni][0] = __float_as_uint(Bs_hi[o0]);
                bh[ni][1] = __float_as_uint(Bs_hi[o1]);
                bl[ni][0] = __float_as_uint(Bs_lo[o0]);
                bl[ni][1] = __float_as_uint(Bs_lo[o1]);
            }
#pragma unroll
            for (int mi = 0; mi < 4; mi++)
#pragma unroll
                for (int ni = 0; ni < 4; ni++) {
                    MMA_TF32(acc[mi][ni], ah[mi][0],ah[mi][1],ah[mi][2],ah[mi][3],
                             bl[ni][0], bl[ni][1]);
                    MMA_TF32(acc[mi][ni], al[mi][0],al[mi][1],al[mi][2],al[mi][3],
                             bh[ni][0], bh[ni][1]);
                    MMA_TF32(acc[mi][ni], ah[mi][0],ah[mi][1],ah[mi][2],ah[mi][3],
                             bh[ni][0], bh[ni][1]);
                }
        }
        __syncthreads();
        if (more) {
            STORES3();
            __syncthreads();
        }
    }

#pragma unroll
    for (int mi = 0; mi < 4; mi++) {
        int rbase = m0 + wm*64 + mi*16 + fr;
#pragma unroll
        for (int half = 0; half < 2; half++) {
            int m = rbase + half*8;
#pragma unroll
            for (int ni = 0; ni < 4; ni++) {
                int n = n0 + wn*32 + ni*8 + fc*2;
                float v0 = acc[mi][ni][half*2 + 0] + bias[n];
                float v1 = acc[mi][ni][half*2 + 1] + bias[n+1];
                if (RES) {
                    v0 += res[(size_t)m * N + n];
                    v1 += res[(size_t)m * N + n + 1];
                }
                *(float2*)(C + (size_t)m * N + n) = make_float2(v0, v1);
            }
        }
    }
#undef LOADG3
#undef SPLIT4
#undef STORES3
}

// ---------------------------------------------------------------- attention (tf32x3 flash)
// Block: 64 q-rows, 128 threads (4 warps, 16 q-rows each). K tiles of 64.
// KT2: K transposed [d][kseq] as {hi,lo} float2 (XOR-swizzled cols); reused for P [q][kseq].
// V2:  V natural [kseq][d] as {hi,lo} float2.
__global__ void __launch_bounds__(128, 2)
attn_mma_kernel(const float* __restrict__ qkv, float* __restrict__ o)
{
    extern __shared__ float2 sm2[];
    float2* KT2 = sm2;               // [64][68]
    float2* V2  = sm2 + 64*68;       // [64][68]

    int qt = blockIdx.x, h = blockIdx.y, b = blockIdx.z;
    int tid = threadIdx.x;
    int lane = tid & 31, warp = tid >> 5;
    int fr = lane >> 2, fc = lane & 3;
    int w16 = warp * 16;
    size_t base = (size_t)b * S_ * (3*D_) + h*DH_;

    // ---- stage Q (scaled by 1/8) into V2 region as floats [q][68]
    float* Qs = (float*)V2;
#pragma unroll
    for (int rep = 0; rep < 8; rep++) {
        int lin = rep*512 + tid*4;
        int r = lin >> 6, d0 = lin & 63;
        float4 q = *(const float4*)(qkv + base + (size_t)(qt*64 + r)*(3*D_) + d0);
        Qs[r*68 + d0 + 0] = q.x * 0.125f;
        Qs[r*68 + d0 + 1] = q.y * 0.125f;
        Qs[r*68 + d0 + 2] = q.z * 0.125f;
        Qs[r*68 + d0 + 3] = q.w * 0.125f;
    }
    __syncthreads();

    // resident Q fragments (hi/lo)
    unsigned qh[8][4], ql[8][4];
#pragma unroll
    for (int kt = 0; kt < 8; kt++) {
        int c0 = kt*8 + fc;
        float v[4];
        v[0] = Qs[(w16+fr  )*68 + c0];
        v[1] = Qs[(w16+fr+8)*68 + c0];
        v[2] = Qs[(w16+fr  )*68 + c0 + 4];
        v[3] = Qs[(w16+fr+8)*68 + c0 + 4];
#pragma unroll
        for (int j = 0; j < 4; j++) {
            qh[kt][j] = f2tf32(v[j]);
            ql[kt][j] = f2tf32(v[j] - __uint_as_float(qh[kt][j]));
        }
    }

    float m0 = -1e30f, m1 = -1e30f, l0 = 0.f, l1 = 0.f;
    float oacc[8][4];
#pragma unroll
    for (int nt = 0; nt < 8; nt++)
#pragma unroll
        for (int j = 0; j < 4; j++) oacc[nt][j] = 0.f;

    for (int ktile = 0; ktile < S_/64; ktile++) {
        __syncthreads();   // prior O-phase reads (and Q staging reads) complete

        // ---- load K (transpose + swizzle + split) and V (split) ----
#pragma unroll
        for (int rep = 0; rep < 8; rep++) {
            int lin = rep*512 + tid*4;
            int r = lin >> 6, d0 = lin & 63;
            size_t row = base + (size_t)(ktile*64 + r)*(3*D_);
            float4 kv = *(const float4*)(qkv + row + D_ + d0);
            float kva[4] = {kv.x, kv.y, kv.z, kv.w};
#pragma unroll
            for (int i = 0; i < 4; i++) {
                int d = d0 + i;
                float hf = rndtf32(kva[i]);
                int col = r ^ ((d >> 2) & 15);
                KT2[d*68 + col] = make_float2(hf, kva[i] - hf);
            }
            float4 vv = *(const float4*)(qkv + row + 2*D_ + d0);
            float vva[4] = {vv.x, vv.y, vv.z, vv.w};
#pragma unroll
            for (int i = 0; i < 4; i++) {
                float hf = rndtf32(vva[i]);
                V2[r*68 + d0 + i] = make_float2(hf, vva[i] - hf);
            }
        }
        __syncthreads();

        // ---- S = Q K^T (tf32x3) ----
        float sacc[8][4];
#pragma unroll
        for (int nt = 0; nt < 8; nt++)
#pragma unroll
            for (int j = 0; j < 4; j++) sacc[nt][j] = 0.f;

#pragma unroll
        for (int kt = 0; kt < 8; kt++) {
            int d0 = kt*8 + fc, d1 = d0 + 4;
            int s0 = (d0 >> 2) & 15, s1 = (d1 >> 2) & 15;
#pragma unroll
            for (int nt = 0; nt < 8; nt++) {
                float2 b0 = KT2[d0*68 + ((nt*8 + fr) ^ s0)];
                float2 b1 = KT2[d1*68 + ((nt*8 + fr) ^ s1)];
                unsigned bh0 = __float_as_uint(b0.x), bl0 = __float_as_uint(b0.y);
                unsigned bh1 = __float_as_uint(b1.x), bl1 = __float_as_uint(b1.y);
                MMA_TF32(sacc[nt], qh[kt][0],qh[kt][1],qh[kt][2],qh[kt][3], bl0, bl1);
                MMA_TF32(sacc[nt], ql[kt][0],ql[kt][1],ql[kt][2],ql[kt][3], bh0, bh1);
                MMA_TF32(sacc[nt], qh[kt][0],qh[kt][1],qh[kt][2],qh[kt][3], bh0, bh1);
            }
        }

        // ---- online softmax (rows fr and fr+8 of this warp's 16) ----
        float rm0 = -1e30f, rm1 = -1e30f;
#pragma unroll
        for (int nt = 0; nt < 8; nt++) {
            rm0 = fmaxf(rm0, fmaxf(sacc[nt][0], sacc[nt][1]));
            rm1 = fmaxf(rm1, fmaxf(sacc[nt][2], sacc[nt][3]));
        }
        rm0 = fmaxf(rm0, __shfl_xor_sync(~0u, rm0, 1));
        rm0 = fmaxf(rm0, __shfl_xor_sync(~0u, rm0, 2));
        rm1 = fmaxf(rm1, __shfl_xor_sync(~0u, rm1, 1));
        rm1 = fmaxf(rm1, __shfl_xor_sync(~0u, rm1, 2));
        float mn0 = fmaxf(m0, rm0), mn1 = fmaxf(m1, rm1);
        float a0 = __expf(m0 - mn0), a1 = __expf(m1 - mn1);
        float sum0 = 0.f, sum1 = 0.f;
#pragma unroll
        for (int nt = 0; nt < 8; nt++) {
            sacc[nt][0] = __expf(sacc[nt][0] - mn0);
            sacc[nt][1] = __expf(sacc[nt][1] - mn0);
            sacc[nt][2] = __expf(sacc[nt][2] - mn1);
            sacc[nt][3] = __expf(sacc[nt][3] - mn1);
            sum0 += sacc[nt][0] + sacc[nt][1];
            sum1 += sacc[nt][2] + sacc[nt][3];
        }
        sum0 += __shfl_xor_sync(~0u, sum0, 1);
        sum0 += __shfl_xor_sync(~0u, sum0, 2);
        sum1 += __shfl_xor_sync(~0u, sum1, 1);
        sum1 += __shfl_xor_sync(~0u, sum1, 2);
        m0 = mn0; m1 = mn1;
        l0 = l0*a0 + sum0;
        l1 = l1*a1 + sum1;
#pragma unroll
        for (int nt = 0; nt < 8; nt++) {
            oacc[nt][0] *= a0; oacc[nt][1] *= a0;
            oacc[nt][2] *= a1; oacc[nt][3] *= a1;
        }

        __syncthreads();   // all S reads of KT2 done before P overwrite

        // ---- store P (hi/lo) into KT2 as [q][kseq], unswizzled ----
#pragma unroll
        for (int nt = 0; nt < 8; nt++) {
#pragma unroll
            for (int j = 0; j < 4; j++) {
                int row = w16 + fr + (j >> 1)*8;
                int col = nt*8 + 2*fc + (j & 1);
                float p = sacc[nt][j];
                float hf = rndtf32(p);
                KT2[row*68 + col] = make_float2(hf, p - hf);
            }
        }
        __syncthreads();

        // ---- O += P V (tf32x3) ----
#pragma unroll
        for (int kt = 0; kt < 8; kt++) {
            float2 A0 = KT2[(w16+fr  )*68 + kt*8 + fc    ];
            float2 A1 = KT2[(w16+fr+8)*68 + kt*8 + fc    ];
            float2 A2 = KT2[(w16+fr  )*68 + kt*8 + fc + 4];
            float2 A3 = KT2[(w16+fr+8)*68 + kt*8 + fc + 4];
            unsigned ph[4] = {__float_as_uint(A0.x), __float_as_uint(A1.x),
                              __float_as_uint(A2.x), __float_as_uint(A3.x)};
            unsigned pl[4] = {__float_as_uint(A0.y), __float_as_uint(A1.y),
                              __float_as_uint(A2.y), __float_as_uint(A3.y)};
#pragma unroll
            for (int nt = 0; nt < 8; nt++) {
                float2 b0 = V2[(kt*8 + fc    )*68 + nt*8 + fr];
                float2 b1 = V2[(kt*8 + fc + 4)*68 + nt*8 + fr];
                unsigned bh0 = __float_as_uint(b0.x), bl0 = __float_as_uint(b0.y);
                unsigned bh1 = __float_as_uint(b1.x), bl1 = __float_as_uint(b1.y);
                MMA_TF32(oacc[nt], ph[0],ph[1],ph[2],ph[3], bl0, bl1);
                MMA_TF32(oacc[nt], pl[0],pl[1],pl[2],pl[3], bh0, bh1);
                MMA_TF32(oacc[nt], ph[0],ph[1],ph[2],ph[3], bh0, bh1);
            }
        }
    }

    // ---- finalize ----
    float inv0 = 1.f / l0, inv1 = 1.f / l1;
    int tok0 = b*S_ + qt*64 + w16 + fr;
#pragma unroll
    for (int nt = 0; nt < 8; nt++) {
        int col = h*DH_ + nt*8 + 2*fc;
        *(float2*)(o + (size_t)tok0*D_ + col) =
            make_float2(oacc[nt][0]*inv0, oacc[nt][1]*inv0);
        *(float2*)(o + (size_t)(tok0+8)*D_ + col) =
            make_float2(oacc[nt][2]*inv1, oacc[nt][3]*inv1);
    }
}

// ---------------------------------------------------------------- gate/top2
__global__ void gate_kernel(const float* __restrict__ xin,
                            const float* __restrict__ wg)
{
    int t = blockIdx.x;
    int tid = threadIdx.x;     // 128
    const float* xr = xin + (size_t)t * D_;
    float acc[E_] = {};
    for (int d = tid; d < D_; d += 128) {
        float xv = xr[d];
        const float* w = wg + d*E_;
#pragma unroll
        for (int e = 0; e < E_; e++) acc[e] = fmaf(xv, w[e], acc[e]);
    }
#pragma unroll
    for (int e = 0; e < E_; e++)
#pragma unroll
        for (int msk = 16; msk; msk >>= 1)
            acc[e] += __shfl_xor_sync(~0u, acc[e], msk);
    __shared__ float red[4][E_];
    if ((tid & 31) == 0)
#pragma unroll
        for (int e = 0; e < E_; e++) red[tid>>5][e] = acc[e];
    __syncthreads();
    if (tid == 0) {
        float lg[E_];
#pragma unroll
        for (int e = 0; e < E_; e++)
            lg[e] = red[0][e] + red[1][e] + red[2][e] + red[3][e];
        int i0 = 0;
#pragma unroll
        for (int e = 1; e < E_; e++) if (lg[e] > lg[i0]) i0 = e;
        int i1 = -1;
#pragma unroll
        for (int e = 0; e < E_; e++)
            if (e != i0 && (i1 < 0 || lg[e] > lg[i1])) i1 = e;
        float d10 = __expf(lg[i1] - lg[i0]);        // <= 1
        float w0 = 1.f / (1.f + d10);
        float w1 = d10 * w0;
        g_tokW[2*t]   = w0;
        g_tokW[2*t+1] = w1;
        int p0 = atomicAdd(&g_cnt[i0], 1);
        g_exTok[i0*T_ + p0] = t;  g_exDst[i0*T_ + p0] = 2*t;
        int p1 = atomicAdd(&g_cnt[i1], 1);
        g_exTok[i1*T_ + p1] = t;  g_exDst[i1*T_ + p1] = 2*t+1;
    }
}

// ---------------------------------------------------------------- combine
__global__ void combine_kernel(const float* __restrict__ x1,
                               float* __restrict__ out)
{
    size_t idx = ((size_t)blockIdx.x * 256 + threadIdx.x) * 4;
    if (idx >= (size_t)T_*D_) return;
    int t = (int)(idx >> 10);
    int c = (int)(idx & (D_-1));
    float w0 = g_tokW[2*t], w1 = g_tokW[2*t+1];
    float4 a  = *(const float4*)(x1 + idx);
    float4 y0 = *(const float4*)(g_ybuf + (size_t)(2*t)*D_ + c);
    float4 y1 = *(const float4*)(g_ybuf + (size_t)(2*t+1)*D_ + c);
    float4 r;
    r.x = a.x + w0*y0.x + w1*y1.x;
    r.y = a.y + w0*y0.y + w1*y1.y;
    r.z = a.z + w0*y0.z + w1*y1.z;
    r.w = a.w + w0*y0.w + w1*y1.w;
    *(float4*)(out + idx) = r;
}

// ---------------------------------------------------------------- launch
extern "C" void kernel_launch(void* const* d_in, const int* in_sizes, int n_in,
                              void* d_out, int out_size)
{
    const float* x      = (const float*)d_in[0];
    const float* ln1_g  = (const float*)d_in[1];
    const float* ln1_b  = (const float*)d_in[2];
    const float* ln2_g  = (const float*)d_in[3];
    const float* ln2_b  = (const float*)d_in[4];
    const float* w_qkv  = (const float*)d_in[5];
    const float* b_qkv  = (const float*)d_in[6];
    const float* w_out  = (const float*)d_in[7];
    const float* b_out  = (const float*)d_in[8];
    const float* w_gate = (const float*)d_in[9];
    const float* w1     = (const float*)d_in[10];
    const float* b1     = (const float*)d_in[11];
    const float* w2     = (const float*)d_in[12];
    const float* b2     = (const float*)d_in[13];
    float* out = (float*)d_out;

    float *p_h, *p_qkv, *p_attn, *p_x1, *p_moein, *p_he, *p_ybuf, *p_w1r, *p_w2r;
    int *p_exTok, *p_exDst, *p_cnt;
    cudaGetSymbolAddress((void**)&p_h,     g_h);
    cudaGetSymbolAddress((void**)&p_qkv,   g_qkv);
    cudaGetSymbolAddress((void**)&p_attn,  g_attn);
    cudaGetSymbolAddress((void**)&p_x1,    g_x1);
    cudaGetSymbolAddress((void**)&p_moein, g_moein);
    cudaGetSymbolAddress((void**)&p_he,    g_he);
    cudaGetSymbolAddress((void**)&p_ybuf,  g_ybuf);
    cudaGetSymbolAddress((void**)&p_w1r,   g_w1r);
    cudaGetSymbolAddress((void**)&p_w2r,   g_w2r);
    cudaGetSymbolAddress((void**)&p_exTok, g_exTok);
    cudaGetSymbolAddress((void**)&p_exDst, g_exDst);
    cudaGetSymbolAddress((void**)&p_cnt,   g_cnt);

    cudaFuncSetAttribute(moe_mma_kernel<true>,
        cudaFuncAttributeMaxDynamicSharedMemorySize, DSMEM_BYTES);
    cudaFuncSetAttribute(moe_mma_kernel<false>,
        cudaFuncAttributeMaxDynamicSharedMemorySize, DSMEM_BYTES);
    cudaFuncSetAttribute(mma3_kernel<false>,
        cudaFuncAttributeMaxDynamicSharedMemorySize, DSMEM_BYTES);
    cudaFuncSetAttribute(mma3_kernel<true>,
        cudaFuncAttributeMaxDynamicSharedMemorySize, DSMEM_BYTES);
    cudaFuncSetAttribute(attn_mma_kernel,
        cudaFuncAttributeMaxDynamicSharedMemorySize, ATTN_SMEM);

    zero_cnt_kernel<<<1, 32>>>();

    // pre-round expert weights to RNA tf32 (independent of everything below)
    round_kernel<<<(E_*D_*DFF_/4 + 255)/256, 256>>>(w1, p_w1r, E_*D_*DFF_/4);
    round_kernel<<<(E_*DFF_*D_/4 + 255)/256, 256>>>(w2, p_w2r, E_*DFF_*D_/4);

    // LN1
    ln_kernel<<<T_, 256>>>(x, ln1_g, ln1_b, p_h);

    // QKV (3xTF32, fp32-grade)
    mma3_kernel<false><<<dim3(3*D_/128, T_/128, 1), 256, DSMEM_BYTES>>>(
        p_h, w_qkv, b_qkv, nullptr, p_qkv, 3*D_, D_);

    // attention (tf32x3 flash)
    attn_mma_kernel<<<dim3(S_/64, H_, B_), 128, ATTN_SMEM>>>(p_qkv, p_attn);

    // out-proj + residual (3xTF32)
    mma3_kernel<true><<<dim3(D_/128, T_/128, 1), 256, DSMEM_BYTES>>>(
        p_attn, w_out, b_out, x, p_x1, D_, D_);

    // LN2
    ln_kernel<<<T_, 256>>>(p_x1, ln2_g, ln2_b, p_moein);

    // gate + routing (fp32, reads moein BEFORE rounding)
    gate_kernel<<<T_, 128>>>(p_moein, w_gate);

    // round moein in place (GEMM1's A operand)
    round_kernel<<<(T_*D_/4 + 255)/256, 256>>>(p_moein, p_moein, T_*D_/4);

    // expert GEMM1: he = rnd(gelu(gather(moein) @ w1r + b1))
    moe_mma_kernel<true><<<dim3(DFF_/128, T_/128, E_), 256, DSMEM_BYTES>>>(
        p_moein, p_w1r, b1, p_he,
        DFF_, D_, p_exTok, p_exDst, p_cnt,
        (size_t)D_*DFF_, DFF_, T_);

    // expert GEMM2: ybuf = gather(he) @ w2r + b2
    moe_mma_kernel<false><<<dim3(D_/128, T_/128, E_), 256, DSMEM_BYTES>>>(
        p_he, p_w2r, b2, p_ybuf,
        D_, DFF_, p_exDst, p_exDst, p_cnt,
        (size_t)DFF_*D_, D_, T_);

    // combine: out = x1 + w0*y0 + w1*y1
    combine_kernel<<<(T_*D_/4 + 255)/256, 256>>>(p_x1, out);
}

// round 5
// speedup vs baseline: 2.5850x; 1.0277x over previous
#include <cuda_runtime.h>
#include <math.h>

#define B_ 4
#define S_ 2048
#define D_ 1024
#define H_ 16
#define DH_ 64
#define E_ 8
#define DFF_ 4096
#define T_ (B_*S_)          // 8192 tokens

// ---------------- scratch (device globals; no cudaMalloc allowed) ----------
__device__ float g_h[(size_t)T_*D_];            // LN1 out
__device__ float g_qkv[(size_t)T_*3*D_];        // qkv
__device__ float g_attn[(size_t)T_*D_];         // attention out
__device__ float g_x1[(size_t)T_*D_];           // post-attn residual
__device__ float g_moein[(size_t)T_*D_];        // LN2 out
__device__ float g_he[(size_t)2*T_*DFF_];       // expert hidden
__device__ float g_ybuf[(size_t)2*T_*D_];       // expert out
__device__ int   g_cnt[E_];
__device__ int   g_exTok[E_*T_];
__device__ int   g_exDst[E_*T_];
__device__ float g_tokW[2*T_];

// smem geometry shared by mma GEMM kernels (floats)
#define AS_SZ (128*36)
#define BS_SZ (32*136)
#define STG_SZ (AS_SZ + BS_SZ)
#define DSMEM_BYTES (2*STG_SZ*4)      // 71680 B (2-stage raw fp32)
#define ATTN_SMEM (2*64*68*8)         // 2 float2 buffers [64][68] = 69632 B

__device__ __forceinline__ unsigned f2tf32(float x) {
    unsigned r;
    asm("cvt.rna.tf32.f32 %0, %1;" : "=r"(r) : "f"(x));
    return r;
}
__device__ __forceinline__ float rndtf32(float x) {
    return __uint_as_float(f2tf32(x));
}
__device__ __forceinline__ void cpasync16(float* dst, const float* src, bool pred) {
    unsigned d = (unsigned)__cvta_generic_to_shared(dst);
    int sz = pred ? 16 : 0;
    asm volatile("cp.async.cg.shared.global [%0], [%1], 16, %2;\n"
                 :: "r"(d), "l"(src), "r"(sz));
}
#define MMA_TF32(c, a0,a1,a2,a3, b0,b1)                                     \
    asm volatile(                                                           \
        "mma.sync.aligned.m16n8k8.row.col.f32.tf32.tf32.f32 "               \
        "{%0,%1,%2,%3}, {%4,%5,%6,%7}, {%8,%9}, {%0,%1,%2,%3};\n"           \
        : "+f"((c)[0]), "+f"((c)[1]), "+f"((c)[2]), "+f"((c)[3])            \
        : "r"(a0), "r"(a1), "r"(a2), "r"(a3), "r"(b0), "r"(b1))

// ---------------------------------------------------------------- zero cnt
__global__ void zero_cnt_kernel() {
    if (threadIdx.x < E_) g_cnt[threadIdx.x] = 0;
}

// ---------------------------------------------------------------- layernorm
__global__ void ln_kernel(const float* __restrict__ x,
                          const float* __restrict__ g,
                          const float* __restrict__ b,
                          float* __restrict__ out) {
    int row = blockIdx.x;
    int t = threadIdx.x;                       // 256 threads
    const float* xr = x + (size_t)row * D_;
    float v[4];
    float s = 0.f, ss = 0.f;
#pragma unroll
    for (int i = 0; i < 4; i++) {
        v[i] = xr[t + i*256];
        s += v[i]; ss += v[i]*v[i];
    }
#pragma unroll
    for (int m = 16; m; m >>= 1) {
        s  += __shfl_xor_sync(~0u, s, m);
        ss += __shfl_xor_sync(~0u, ss, m);
    }
    __shared__ float rs[8], rss[8];
    if ((t & 31) == 0) { rs[t>>5] = s; rss[t>>5] = ss; }
    __syncthreads();
    float sum = 0.f, sumsq = 0.f;
#pragma unroll
    for (int i = 0; i < 8; i++) { sum += rs[i]; sumsq += rss[i]; }
    float mean = sum * (1.f/D_);
    float var  = sumsq * (1.f/D_) - mean*mean;
    float rstd = rsqrtf(var + 1e-5f);
    float* orow = out + (size_t)row * D_;
#pragma unroll
    for (int i = 0; i < 4; i++) {
        int c = t + i*256;
        orow[c] = (v[i]-mean)*rstd*g[c] + b[c];
    }
}

// ---------------------------------------------------------------- MoE mma
// C[scatter(m),n] = act(gather(A) @ B_e + bias_e); RNA tf32 rounding AT LOAD.
// 128x128x32 block, 8 warps (2M x 4N), cp.async 2-stage, raw fp32 smem.
template<bool GELU>
__global__ void __launch_bounds__(256, 2)
moe_mma_kernel(const float* __restrict__ A,
               const float* __restrict__ Bw,
               const float* __restrict__ bias,
               float* __restrict__ C,
               int N, int K,
               const int* __restrict__ gatherA,
               const int* __restrict__ scatterC,
               const int* __restrict__ cnt,
               size_t bStride, int biasStride, int listStride)
{
    extern __shared__ float smem[];
    int e = blockIdx.z;
    int Me = cnt[e];
    int m0 = blockIdx.y * 128;
    if (m0 >= Me) return;
    int n0 = blockIdx.x * 128;

    const float* Bp    = Bw + (size_t)e * bStride;
    const float* biasp = bias + (size_t)e * biasStride;
    const int*   gA    = gatherA  + (size_t)e * listStride;
    const int*   sC    = scatterC + (size_t)e * listStride;

    int tid = threadIdx.x, lane = tid & 31, warp = tid >> 5;
    int wm = warp >> 2, wn = warp & 3;
    int fr = lane >> 2, fc = lane & 3;

    int aRowBase = tid >> 3;           // +i*32
    int aKq = (tid & 7) * 4;
    const float* aSrc[4]; bool aValid[4];
#pragma unroll
    for (int i = 0; i < 4; i++) {
        int r = aRowBase + i*32;
        int rowA = m0 + r;
        aValid[i] = rowA < Me;
        aSrc[i] = aValid[i] ? (A + (size_t)gA[rowA]*K + aKq) : A;
    }
    int bKBase = tid >> 5;             // +i*8
    int bn4 = (tid & 31) * 4;
    const float* bSrc[4];
#pragma unroll
    for (int i = 0; i < 4; i++)
        bSrc[i] = Bp + (size_t)(bKBase + i*8)*N + n0 + bn4;

    float acc[4][4][4];
#pragma unroll
    for (int mi = 0; mi < 4; mi++)
#pragma unroll
        for (int ni = 0; ni < 4; ni++)
#pragma unroll
            for (int j = 0; j < 4; j++) acc[mi][ni][j] = 0.f;

    int nk = K >> 5;

    auto prefetch = [&](int s, int kt) {
        float* As_ = smem + s*STG_SZ;
        float* Bs_ = As_ + AS_SZ;
#pragma unroll
        for (int i = 0; i < 4; i++)
            cpasync16(As_ + (aRowBase + i*32)*36 + aKq,
                      aSrc[i] + (size_t)kt*32, aValid[i]);
#pragma unroll
        for (int i = 0; i < 4; i++)
            cpasync16(Bs_ + (bKBase + i*8)*136 + bn4,
                      bSrc[i] + (size_t)kt*32*N, true);
        asm volatile("cp.async.commit_group;\n");
    };

    prefetch(0, 0);

    for (int kt = 0; kt < nk; kt++) {
        int s = kt & 1;
        bool more = (kt + 1) < nk;
        if (more) prefetch(s ^ 1, kt + 1);
        if (more) asm volatile("cp.async.wait_group 1;\n");
        else      asm volatile("cp.async.wait_group 0;\n");
        __syncthreads();

        const float* As_ = smem + s*STG_SZ;
        const float* Bs_ = As_ + AS_SZ;
#pragma unroll
        for (int kk8 = 0; kk8 < 4; kk8++) {
            int kk = kk8 * 8;
            unsigned af[4][4], bf[4][2];
#pragma unroll
            for (int mi = 0; mi < 4; mi++) {
                int mb = wm*64 + mi*16;
                af[mi][0] = f2tf32(As_[(mb + fr    )*36 + kk + fc    ]);
                af[mi][1] = f2tf32(As_[(mb + fr + 8)*36 + kk + fc    ]);
                af[mi][2] = f2tf32(As_[(mb + fr    )*36 + kk + fc + 4]);
                af[mi][3] = f2tf32(As_[(mb + fr + 8)*36 + kk + fc + 4]);
            }
#pragma unroll
            for (int ni = 0; ni < 4; ni++) {
                int cb = wn*32 + ni*8;
                bf[ni][0] = f2tf32(Bs_[(kk + fc    )*136 + cb + fr]);
                bf[ni][1] = f2tf32(Bs_[(kk + fc + 4)*136 + cb + fr]);
            }
#pragma unroll
            for (int mi = 0; mi < 4; mi++)
#pragma unroll
                for (int ni = 0; ni < 4; ni++)
                    MMA_TF32(acc[mi][ni], af[mi][0],af[mi][1],af[mi][2],af[mi][3],
                             bf[ni][0], bf[ni][1]);
        }
        __syncthreads();
    }

#pragma unroll
    for (int mi = 0; mi < 4; mi++) {
        int rbase = m0 + wm*64 + mi*16 + fr;
#pragma unroll
        for (int half = 0; half < 2; half++) {
            int m = rbase + half*8;
            if (m >= Me) continue;
            int crow = sC[m];
#pragma unroll
            for (int ni = 0; ni < 4; ni++) {
                int n = n0 + wn*32 + ni*8 + fc*2;
                float v0 = acc[mi][ni][half*2 + 0] + biasp[n];
                float v1 = acc[mi][ni][half*2 + 1] + biasp[n+1];
                if (GELU) {
                    float u = v0;
                    v0 = 0.5f*u*(1.f + tanhf(0.7978845608028654f*(u + 0.044715f*u*u*u)));
                    u = v1;
                    v1 = 0.5f*u*(1.f + tanhf(0.7978845608028654f*(u + 0.044715f*u*u*u)));
                }
                *(float2*)(C + (size_t)crow * N + n) = make_float2(v0, v1);
            }
        }
    }
}

// ---------------------------------------------------------------- 3xTF32 dense GEMM v2
// fp32-grade GEMM: hi/lo tf32 split AT FRAGMENT LOAD (drops lo*lo, err ~2^-22).
// 128x128x32 block, 8 warps (2M x 4N), cp.async 2-stage, raw fp32 smem.
template<bool RES>
__global__ void __launch_bounds__(256, 2)
mma3_kernel(const float* __restrict__ A,
            const float* __restrict__ Bw,
            const float* __restrict__ bias,
            const float* __restrict__ res,
            float* __restrict__ C,
            int N, int K)
{
    extern __shared__ float smem[];
    int m0 = blockIdx.y * 128;
    int n0 = blockIdx.x * 128;

    int tid = threadIdx.x, lane = tid & 31, warp = tid >> 5;
    int wm = warp >> 2, wn = warp & 3;
    int fr = lane >> 2, fc = lane & 3;

    int aRowBase = tid >> 3;
    int aKq = (tid & 7) * 4;
    const float* aSrc[4];
#pragma unroll
    for (int i = 0; i < 4; i++)
        aSrc[i] = A + (size_t)(m0 + aRowBase + i*32)*K + aKq;
    int bKBase = tid >> 5;
    int bn4 = (tid & 31) * 4;
    const float* bSrc[4];
#pragma unroll
    for (int i = 0; i < 4; i++)
        bSrc[i] = Bw + (size_t)(bKBase + i*8)*N + n0 + bn4;

    float acc[4][4][4];
#pragma unroll
    for (int mi = 0; mi < 4; mi++)
#pragma unroll
        for (int ni = 0; ni < 4; ni++)
#pragma unroll
            for (int j = 0; j < 4; j++) acc[mi][ni][j] = 0.f;

    int nk = K >> 5;

    auto prefetch = [&](int s, int kt) {
        float* As_ = smem + s*STG_SZ;
        float* Bs_ = As_ + AS_SZ;
#pragma unroll
        for (int i = 0; i < 4; i++)
            cpasync16(As_ + (aRowBase + i*32)*36 + aKq,
                      aSrc[i] + (size_t)kt*32, true);
#pragma unroll
        for (int i = 0; i < 4; i++)
            cpasync16(Bs_ + (bKBase + i*8)*136 + bn4,
                      bSrc[i] + (size_t)kt*32*N, true);
        asm volatile("cp.async.commit_group;\n");
    };

    prefetch(0, 0);

    for (int kt = 0; kt < nk; kt++) {
        int s = kt & 1;
        bool more = (kt + 1) < nk;
        if (more) prefetch(s ^ 1, kt + 1);
        if (more) asm volatile("cp.async.wait_group 1;\n");
        else      asm volatile("cp.async.wait_group 0;\n");
        __syncthreads();

        const float* As_ = smem + s*STG_SZ;
        const float* Bs_ = As_ + AS_SZ;
#pragma unroll
        for (int kk8 = 0; kk8 < 4; kk8++) {
            int kk = kk8 * 8;
            unsigned ah[4][4], al[4][4], bh[4][2], bl[4][2];
#pragma unroll
            for (int mi = 0; mi < 4; mi++) {
                int mb = wm*64 + mi*16;
                float v0 = As_[(mb + fr    )*36 + kk + fc    ];
                float v1 = As_[(mb + fr + 8)*36 + kk + fc    ];
                float v2 = As_[(mb + fr    )*36 + kk + fc + 4];
                float v3 = As_[(mb + fr + 8)*36 + kk + fc + 4];
                ah[mi][0] = f2tf32(v0); al[mi][0] = f2tf32(v0 - __uint_as_float(ah[mi][0]));
                ah[mi][1] = f2tf32(v1); al[mi][1] = f2tf32(v1 - __uint_as_float(ah[mi][1]));
                ah[mi][2] = f2tf32(v2); al[mi][2] = f2tf32(v2 - __uint_as_float(ah[mi][2]));
                ah[mi][3] = f2tf32(v3); al[mi][3] = f2tf32(v3 - __uint_as_float(ah[mi][3]));
            }
#pragma unroll
            for (int ni = 0; ni < 4; ni++) {
                int cb = wn*32 + ni*8;
                float u0 = Bs_[(kk + fc    )*136 + cb + fr];
                float u1 = Bs_[(kk + fc + 4)*136 + cb + fr];
                bh[ni][0] = f2tf32(u0); bl[ni][0] = f2tf32(u0 - __uint_as_float(bh[ni][0]));
                bh[ni][1] = f2tf32(u1); bl[ni][1] = f2tf32(u1 - __uint_as_float(bh[ni][1]));
            }
#pragma unroll
            for (int mi = 0; mi < 4; mi++)
#pragma unroll
                for (int ni = 0; ni < 4; ni++) {
                    MMA_TF32(acc[mi][ni], ah[mi][0],ah[mi][1],ah[mi][2],ah[mi][3],
                             bl[ni][0], bl[ni][1]);
                    MMA_TF32(acc[mi][ni], al[mi][0],al[mi][1],al[mi][2],al[mi][3],
                             bh[ni][0], bh[ni][1]);
                    MMA_TF32(acc[mi][ni], ah[mi][0],ah[mi][1],ah[mi][2],ah[mi][3],
                             bh[ni][0], bh[ni][1]);
                }
        }
        __syncthreads();
    }

#pragma unroll
    for (int mi = 0; mi < 4; mi++) {
        int rbase = m0 + wm*64 + mi*16 + fr;
#pragma unroll
        for (int half = 0; half < 2; half++) {
            int m = rbase + half*8;
#pragma unroll
            for (int ni = 0; ni < 4; ni++) {
                int n = n0 + wn*32 + ni*8 + fc*2;
                float v0 = acc[mi][ni][half*2 + 0] + bias[n];
                float v1 = acc[mi][ni][half*2 + 1] + bias[n+1];
                if (RES) {
                    v0 += res[(size_t)m * N + n];
                    v1 += res[(size_t)m * N + n + 1];
                }
                *(float2*)(C + (size_t)m * N + n) = make_float2(v0, v1);
            }
        }
    }
}

// ---------------------------------------------------------------- attention (tf32x3 flash)
// Block: 64 q-rows, 128 threads (4 warps, 16 q-rows each). K tiles of 64.
// KT2: K transposed [d][kseq] as {hi,lo} float2 (XOR-swizzled cols); reused for P [q][kseq].
// V2:  V natural [kseq][d] as {hi,lo} float2.
__global__ void __launch_bounds__(128, 2)
attn_mma_kernel(const float* __restrict__ qkv, float* __restrict__ o)
{
    extern __shared__ float2 sm2[];
    float2* KT2 = sm2;               // [64][68]
    float2* V2  = sm2 + 64*68;       // [64][68]

    int qt = blockIdx.x, h = blockIdx.y, b = blockIdx.z;
    int tid = threadIdx.x;
    int lane = tid & 31, warp = tid >> 5;
    int fr = lane >> 2, fc = lane & 3;
    int w16 = warp * 16;
    size_t base = (size_t)b * S_ * (3*D_) + h*DH_;

    // ---- stage Q (scaled by 1/8) into V2 region as floats [q][68]
    float* Qs = (float*)V2;
#pragma unroll
    for (int rep = 0; rep < 8; rep++) {
        int lin = rep*512 + tid*4;
        int r = lin >> 6, d0 = lin & 63;
        float4 q = *(const float4*)(qkv + base + (size_t)(qt*64 + r)*(3*D_) + d0);
        Qs[r*68 + d0 + 0] = q.x * 0.125f;
        Qs[r*68 + d0 + 1] = q.y * 0.125f;
        Qs[r*68 + d0 + 2] = q.z * 0.125f;
        Qs[r*68 + d0 + 3] = q.w * 0.125f;
    }
    __syncthreads();

    // resident Q fragments (hi/lo)
    unsigned qh[8][4], ql[8][4];
#pragma unroll
    for (int kt = 0; kt < 8; kt++) {
        int c0 = kt*8 + fc;
        float v[4];
        v[0] = Qs[(w16+fr  )*68 + c0];
        v[1] = Qs[(w16+fr+8)*68 + c0];
        v[2] = Qs[(w16+fr  )*68 + c0 + 4];
        v[3] = Qs[(w16+fr+8)*68 + c0 + 4];
#pragma unroll
        for (int j = 0; j < 4; j++) {
            qh[kt][j] = f2tf32(v[j]);
            ql[kt][j] = f2tf32(v[j] - __uint_as_float(qh[kt][j]));
        }
    }

    float m0 = -1e30f, m1 = -1e30f, l0 = 0.f, l1 = 0.f;
    float oacc[8][4];
#pragma unroll
    for (int nt = 0; nt < 8; nt++)
#pragma unroll
        for (int j = 0; j < 4; j++) oacc[nt][j] = 0.f;

    for (int ktile = 0; ktile < S_/64; ktile++) {
        __syncthreads();   // prior O-phase reads (and Q staging reads) complete

        // ---- load K (transpose + swizzle + split) and V (split) ----
#pragma unroll
        for (int rep = 0; rep < 8; rep++) {
            int lin = rep*512 + tid*4;
            int r = lin >> 6, d0 = lin & 63;
            size_t row = base + (size_t)(ktile*64 + r)*(3*D_);
            float4 kv = *(const float4*)(qkv + row + D_ + d0);
            float kva[4] = {kv.x, kv.y, kv.z, kv.w};
#pragma unroll
            for (int i = 0; i < 4; i++) {
                int d = d0 + i;
                float hf = rndtf32(kva[i]);
                int col = r ^ ((d >> 2) & 15);
                KT2[d*68 + col] = make_float2(hf, kva[i] - hf);
            }
            float4 vv = *(const float4*)(qkv + row + 2*D_ + d0);
            float vva[4] = {vv.x, vv.y, vv.z, vv.w};
#pragma unroll
            for (int i = 0; i < 4; i++) {
                float hf = rndtf32(vva[i]);
                V2[r*68 + d0 + i] = make_float2(hf, vva[i] - hf);
            }
        }
        __syncthreads();

        // ---- S = Q K^T (tf32x3) ----
        float sacc[8][4];
#pragma unroll
        for (int nt = 0; nt < 8; nt++)
#pragma unroll
            for (int j = 0; j < 4; j++) sacc[nt][j] = 0.f;

#pragma unroll
        for (int kt = 0; kt < 8; kt++) {
            int d0 = kt*8 + fc, d1 = d0 + 4;
            int s0 = (d0 >> 2) & 15, s1 = (d1 >> 2) & 15;
#pragma unroll
            for (int nt = 0; nt < 8; nt++) {
                float2 b0 = KT2[d0*68 + ((nt*8 + fr) ^ s0)];
                float2 b1 = KT2[d1*68 + ((nt*8 + fr) ^ s1)];
                unsigned bh0 = __float_as_uint(b0.x), bl0 = __float_as_uint(b0.y);
                unsigned bh1 = __float_as_uint(b1.x), bl1 = __float_as_uint(b1.y);
                MMA_TF32(sacc[nt], qh[kt][0],qh[kt][1],qh[kt][2],qh[kt][3], bl0, bl1);
                MMA_TF32(sacc[nt], ql[kt][0],ql[kt][1],ql[kt][2],ql[kt][3], bh0, bh1);
                MMA_TF32(sacc[nt], qh[kt][0],qh[kt][1],qh[kt][2],qh[kt][3], bh0, bh1);
            }
        }

        // ---- online softmax (rows fr and fr+8 of this warp's 16) ----
        float rm0 = -1e30f, rm1 = -1e30f;
#pragma unroll
        for (int nt = 0; nt < 8; nt++) {
            rm0 = fmaxf(rm0, fmaxf(sacc[nt][0], sacc[nt][1]));
            rm1 = fmaxf(rm1, fmaxf(sacc[nt][2], sacc[nt][3]));
        }
        rm0 = fmaxf(rm0, __shfl_xor_sync(~0u, rm0, 1));
        rm0 = fmaxf(rm0, __shfl_xor_sync(~0u, rm0, 2));
        rm1 = fmaxf(rm1, __shfl_xor_sync(~0u, rm1, 1));
        rm1 = fmaxf(rm1, __shfl_xor_sync(~0u, rm1, 2));
        float mn0 = fmaxf(m0, rm0), mn1 = fmaxf(m1, rm1);
        float a0 = __expf(m0 - mn0), a1 = __expf(m1 - mn1);
        float sum0 = 0.f, sum1 = 0.f;
#pragma unroll
        for (int nt = 0; nt < 8; nt++) {
            sacc[nt][0] = __expf(sacc[nt][0] - mn0);
            sacc[nt][1] = __expf(sacc[nt][1] - mn0);
            sacc[nt][2] = __expf(sacc[nt][2] - mn1);
            sacc[nt][3] = __expf(sacc[nt][3] - mn1);
            sum0 += sacc[nt][0] + sacc[nt][1];
            sum1 += sacc[nt][2] + sacc[nt][3];
        }
        sum0 += __shfl_xor_sync(~0u, sum0, 1);
        sum0 += __shfl_xor_sync(~0u, sum0, 2);
        sum1 += __shfl_xor_sync(~0u, sum1, 1);
        sum1 += __shfl_xor_sync(~0u, sum1, 2);
        m0 = mn0; m1 = mn1;
        l0 = l0*a0 + sum0;
        l1 = l1*a1 + sum1;
#pragma unroll
        for (int nt = 0; nt < 8; nt++) {
            oacc[nt][0] *= a0; oacc[nt][1] *= a0;
            oacc[nt][2] *= a1; oacc[nt][3] *= a1;
        }

        __syncthreads();   // all S reads of KT2 done before P overwrite

        // ---- store P (hi/lo) into KT2 as [q][kseq], unswizzled ----
#pragma unroll
        for (int nt = 0; nt < 8; nt++) {
#pragma unroll
            for (int j = 0; j < 4; j++) {
                int row = w16 + fr + (j >> 1)*8;
                int col = nt*8 + 2*fc + (j & 1);
                float p = sacc[nt][j];
                float hf = rndtf32(p);
                KT2[row*68 + col] = make_float2(hf, p - hf);
            }
        }
        __syncthreads();

        // ---- O += P V (tf32x3) ----
#pragma unroll
        for (int kt = 0; kt < 8; kt++) {
            float2 A0 = KT2[(w16+fr  )*68 + kt*8 + fc    ];
            float2 A1 = KT2[(w16+fr+8)*68 + kt*8 + fc    ];
            float2 A2 = KT2[(w16+fr  )*68 + kt*8 + fc + 4];
            float2 A3 = KT2[(w16+fr+8)*68 + kt*8 + fc + 4];
            unsigned ph[4] = {__float_as_uint(A0.x), __float_as_uint(A1.x),
                              __float_as_uint(A2.x), __float_as_uint(A3.x)};
            unsigned pl[4] = {__float_as_uint(A0.y), __float_as_uint(A1.y),
                              __float_as_uint(A2.y), __float_as_uint(A3.y)};
#pragma unroll
            for (int nt = 0; nt < 8; nt++) {
                float2 b0 = V2[(kt*8 + fc    )*68 + nt*8 + fr];
                float2 b1 = V2[(kt*8 + fc + 4)*68 + nt*8 + fr];
                unsigned bh0 = __float_as_uint(b0.x), bl0 = __float_as_uint(b0.y);
                unsigned bh1 = __float_as_uint(b1.x), bl1 = __float_as_uint(b1.y);
                MMA_TF32(oacc[nt], ph[0],ph[1],ph[2],ph[3], bl0, bl1);
                MMA_TF32(oacc[nt], pl[0],pl[1],pl[2],pl[3], bh0, bh1);
                MMA_TF32(oacc[nt], ph[0],ph[1],ph[2],ph[3], bh0, bh1);
            }
        }
    }

    // ---- finalize ----
    float inv0 = 1.f / l0, inv1 = 1.f / l1;
    int tok0 = b*S_ + qt*64 + w16 + fr;
#pragma unroll
    for (int nt = 0; nt < 8; nt++) {
        int col = h*DH_ + nt*8 + 2*fc;
        *(float2*)(o + (size_t)tok0*D_ + col) =
            make_float2(oacc[nt][0]*inv0, oacc[nt][1]*inv0);
        *(float2*)(o + (size_t)(tok0+8)*D_ + col) =
            make_float2(oacc[nt][2]*inv1, oacc[nt][3]*inv1);
    }
}

// ---------------------------------------------------------------- gate/top2
__global__ void gate_kernel(const float* __restrict__ xin,
                            const float* __restrict__ wg)
{
    int t = blockIdx.x;
    int tid = threadIdx.x;     // 128
    const float* xr = xin + (size_t)t * D_;
    float acc[E_] = {};
    for (int d = tid; d < D_; d += 128) {
        float xv = xr[d];
        const float* w = wg + d*E_;
#pragma unroll
        for (int e = 0; e < E_; e++) acc[e] = fmaf(xv, w[e], acc[e]);
    }
#pragma unroll
    for (int e = 0; e < E_; e++)
#pragma unroll
        for (int msk = 16; msk; msk >>= 1)
            acc[e] += __shfl_xor_sync(~0u, acc[e], msk);
    __shared__ float red[4][E_];
    if ((tid & 31) == 0)
#pragma unroll
        for (int e = 0; e < E_; e++) red[tid>>5][e] = acc[e];
    __syncthreads();
    if (tid == 0) {
        float lg[E_];
#pragma unroll
        for (int e = 0; e < E_; e++)
            lg[e] = red[0][e] + red[1][e] + red[2][e] + red[3][e];
        int i0 = 0;
#pragma unroll
        for (int e = 1; e < E_; e++) if (lg[e] > lg[i0]) i0 = e;
        int i1 = -1;
#pragma unroll
        for (int e = 0; e < E_; e++)
            if (e != i0 && (i1 < 0 || lg[e] > lg[i1])) i1 = e;
        float d10 = __expf(lg[i1] - lg[i0]);        // <= 1
        float w0 = 1.f / (1.f + d10);
        float w1 = d10 * w0;
        g_tokW[2*t]   = w0;
        g_tokW[2*t+1] = w1;
        int p0 = atomicAdd(&g_cnt[i0], 1);
        g_exTok[i0*T_ + p0] = t;  g_exDst[i0*T_ + p0] = 2*t;
        int p1 = atomicAdd(&g_cnt[i1], 1);
        g_exTok[i1*T_ + p1] = t;  g_exDst[i1*T_ + p1] = 2*t+1;
    }
}

// ---------------------------------------------------------------- combine
__global__ void combine_kernel(const float* __restrict__ x1,
                               float* __restrict__ out)
{
    size_t idx = ((size_t)blockIdx.x * 256 + threadIdx.x) * 4;
    if (idx >= (size_t)T_*D_) return;
    int t = (int)(idx >> 10);
    int c = (int)(idx & (D_-1));
    float w0 = g_tokW[2*t], w1 = g_tokW[2*t+1];
    float4 a  = *(const float4*)(x1 + idx);
    float4 y0 = *(const float4*)(g_ybuf + (size_t)(2*t)*D_ + c);
    float4 y1 = *(const float4*)(g_ybuf + (size_t)(2*t+1)*D_ + c);
    float4 r;
    r.x = a.x + w0*y0.x + w1*y1.x;
    r.y = a.y + w0*y0.y + w1*y1.y;
    r.z = a.z + w0*y0.z + w1*y1.z;
    r.w = a.w + w0*y0.w + w1*y1.w;
    *(float4*)(out + idx) = r;
}

// ---------------------------------------------------------------- launch
extern "C" void kernel_launch(void* const* d_in, const int* in_sizes, int n_in,
                              void* d_out, int out_size)
{
    const float* x      = (const float*)d_in[0];
    const float* ln1_g  = (const float*)d_in[1];
    const float* ln1_b  = (const float*)d_in[2];
    const float* ln2_g  = (const float*)d_in[3];
    const float* ln2_b  = (const float*)d_in[4];
    const float* w_qkv  = (const float*)d_in[5];
    const float* b_qkv  = (const float*)d_in[6];
    const float* w_out  = (const float*)d_in[7];
    const float* b_out  = (const float*)d_in[8];
    const float* w_gate = (const float*)d_in[9];
    const float* w1     = (const float*)d_in[10];
    const float* b1     = (const float*)d_in[11];
    const float* w2     = (const float*)d_in[12];
    const float* b2     = (const float*)d_in[13];
    float* out = (float*)d_out;

    float *p_h, *p_qkv, *p_attn, *p_x1, *p_moein, *p_he, *p_ybuf;
    int *p_exTok, *p_exDst, *p_cnt;
    cudaGetSymbolAddress((void**)&p_h,     g_h);
    cudaGetSymbolAddress((void**)&p_qkv,   g_qkv);
    cudaGetSymbolAddress((void**)&p_attn,  g_attn);
    cudaGetSymbolAddress((void**)&p_x1,    g_x1);
    cudaGetSymbolAddress((void**)&p_moein, g_moein);
    cudaGetSymbolAddress((void**)&p_he,    g_he);
    cudaGetSymbolAddress((void**)&p_ybuf,  g_ybuf);
    cudaGetSymbolAddress((void**)&p_exTok, g_exTok);
    cudaGetSymbolAddress((void**)&p_exDst, g_exDst);
    cudaGetSymbolAddress((void**)&p_cnt,   g_cnt);

    cudaFuncSetAttribute(moe_mma_kernel<true>,
        cudaFuncAttributeMaxDynamicSharedMemorySize, DSMEM_BYTES);
    cudaFuncSetAttribute(moe_mma_kernel<false>,
        cudaFuncAttributeMaxDynamicSharedMemorySize, DSMEM_BYTES);
    cudaFuncSetAttribute(mma3_kernel<false>,
        cudaFuncAttributeMaxDynamicSharedMemorySize, DSMEM_BYTES);
    cudaFuncSetAttribute(mma3_kernel<true>,
        cudaFuncAttributeMaxDynamicSharedMemorySize, DSMEM_BYTES);
    cudaFuncSetAttribute(attn_mma_kernel,
        cudaFuncAttributeMaxDynamicSharedMemorySize, ATTN_SMEM);

    zero_cnt_kernel<<<1, 32>>>();

    // LN1
    ln_kernel<<<T_, 256>>>(x, ln1_g, ln1_b, p_h);

    // QKV (3xTF32, fp32-grade)
    mma3_kernel<false><<<dim3(3*D_/128, T_/128, 1), 256, DSMEM_BYTES>>>(
        p_h, w_qkv, b_qkv, nullptr, p_qkv, 3*D_, D_);

    // attention (tf32x3 flash)
    attn_mma_kernel<<<dim3(S_/64, H_, B_), 128, ATTN_SMEM>>>(p_qkv, p_attn);

    // out-proj + residual (3xTF32)
    mma3_kernel<true><<<dim3(D_/128, T_/128, 1), 256, DSMEM_BYTES>>>(
        p_attn, w_out, b_out, x, p_x1, D_, D_);

    // LN2
    ln_kernel<<<T_, 256>>>(p_x1, ln2_g, ln2_b, p_moein);

    // gate + routing (fp32, reads unrounded moein)
    gate_kernel<<<T_, 128>>>(p_moein, w_gate);

    // expert GEMM1: he = gelu(rnd(gather(moein)) @ rnd(w1) + b1)   (round-at-load)
    moe_mma_kernel<true><<<dim3(DFF_/128, T_/128, E_), 256, DSMEM_BYTES>>>(
        p_moein, w1, b1, p_he,
        DFF_, D_, p_exTok, p_exDst, p_cnt,
        (size_t)D_*DFF_, DFF_, T_);

    // expert GEMM2: ybuf = rnd(gather(he)) @ rnd(w2) + b2          (round-at-load)
    moe_mma_kernel<false><<<dim3(D_/128, T_/128, E_), 256, DSMEM_BYTES>>>(
        p_he, w2, b2, p_ybuf,
        D_, DFF_, p_exDst, p_exDst, p_cnt,
        (size_t)DFF_*D_, D_, T_);

    // combine: out = x1 + w0*y0 + w1*y1
    combine_kernel<<<(T_*D_/4 + 255)/256, 256>>>(p_x1, out);
}

// round 6
// speedup vs baseline: 2.6228x; 1.0146x over previous
#include <cuda_runtime.h>
#include <math.h>

#define B_ 4
#define S_ 2048
#define D_ 1024
#define H_ 16
#define DH_ 64
#define E_ 8
#define DFF_ 4096
#define T_ (B_*S_)          // 8192 tokens

// ---------------- scratch (device globals; no cudaMalloc allowed) ----------
__device__ float g_h[(size_t)T_*D_];            // LN1 out
__device__ float g_qkv[(size_t)T_*3*D_];        // qkv
__device__ float g_attn[(size_t)T_*D_];         // attention out
__device__ float g_x1[(size_t)T_*D_];           // post-attn residual
__device__ float g_moein[(size_t)T_*D_];        // LN2 out
__device__ float g_he[(size_t)2*T_*DFF_];       // expert hidden
__device__ float g_ybuf[(size_t)2*T_*D_];       // expert out
__device__ int   g_cnt[E_];
__device__ int   g_exTok[E_*T_];
__device__ int   g_exDst[E_*T_];
__device__ float g_tokW[2*T_];

// smem geometry shared by mma GEMM kernels (floats)
#define AS_SZ (128*36)
#define BS_SZ (32*136)
#define STG_SZ (AS_SZ + BS_SZ)
#define DSMEM_BYTES (2*STG_SZ*4)      // 71680 B (2-stage raw fp32)
#define ATTN_SMEM (2*64*68*8)         // 2 float2 buffers [64][68] = 69632 B

__device__ __forceinline__ unsigned f2tf32(float x) {
    unsigned r;
    asm("cvt.rna.tf32.f32 %0, %1;" : "=r"(r) : "f"(x));
    return r;
}
__device__ __forceinline__ float rndtf32(float x) {
    return __uint_as_float(f2tf32(x));
}
__device__ __forceinline__ void cpasync16(float* dst, const float* src, bool pred) {
    unsigned d = (unsigned)__cvta_generic_to_shared(dst);
    int sz = pred ? 16 : 0;
    asm volatile("cp.async.cg.shared.global [%0], [%1], 16, %2;\n"
                 :: "r"(d), "l"(src), "r"(sz));
}
#define MMA_TF32(c, a0,a1,a2,a3, b0,b1)                                     \
    asm volatile(                                                           \
        "mma.sync.aligned.m16n8k8.row.col.f32.tf32.tf32.f32 "               \
        "{%0,%1,%2,%3}, {%4,%5,%6,%7}, {%8,%9}, {%0,%1,%2,%3};\n"           \
        : "+f"((c)[0]), "+f"((c)[1]), "+f"((c)[2]), "+f"((c)[3])            \
        : "r"(a0), "r"(a1), "r"(a2), "r"(a3), "r"(b0), "r"(b1))

// ---------------------------------------------------------------- zero cnt
__global__ void zero_cnt_kernel() {
    if (threadIdx.x < E_) g_cnt[threadIdx.x] = 0;
}

// ---------------------------------------------------------------- layernorm
__global__ void ln_kernel(const float* __restrict__ x,
                          const float* __restrict__ g,
                          const float* __restrict__ b,
                          float* __restrict__ out) {
    int row = blockIdx.x;
    int t = threadIdx.x;                       // 256 threads, 4 floats each
    const float* xr = x + (size_t)row * D_;
    float4 v = *(const float4*)(xr + t*4);
    float s = v.x + v.y + v.z + v.w;
    float ss = v.x*v.x + v.y*v.y + v.z*v.z + v.w*v.w;
#pragma unroll
    for (int m = 16; m; m >>= 1) {
        s  += __shfl_xor_sync(~0u, s, m);
        ss += __shfl_xor_sync(~0u, ss, m);
    }
    __shared__ float rs[8], rss[8];
    if ((t & 31) == 0) { rs[t>>5] = s; rss[t>>5] = ss; }
    __syncthreads();
    float sum = 0.f, sumsq = 0.f;
#pragma unroll
    for (int i = 0; i < 8; i++) { sum += rs[i]; sumsq += rss[i]; }
    float mean = sum * (1.f/D_);
    float var  = sumsq * (1.f/D_) - mean*mean;
    float rstd = rsqrtf(var + 1e-5f);
    float4 gv = *(const float4*)(g + t*4);
    float4 bv = *(const float4*)(b + t*4);
    float4 o;
    o.x = (v.x-mean)*rstd*gv.x + bv.x;
    o.y = (v.y-mean)*rstd*gv.y + bv.y;
    o.z = (v.z-mean)*rstd*gv.z + bv.z;
    o.w = (v.w-mean)*rstd*gv.w + bv.w;
    *(float4*)(out + (size_t)row * D_ + t*4) = o;
}

// ---------------------------------------------------------------- MoE mma
// C[scatter(m),n] = act(gather(A) @ B_e + bias_e); RNA tf32 rounding AT LOAD.
// 128x128x32 block, 8 warps (2M x 4N), cp.async 2-stage, raw fp32 smem.
template<bool GELU>
__global__ void __launch_bounds__(256, 2)
moe_mma_kernel(const float* __restrict__ A,
               const float* __restrict__ Bw,
               const float* __restrict__ bias,
               float* __restrict__ C,
               int N, int K,
               const int* __restrict__ gatherA,
               const int* __restrict__ scatterC,
               const int* __restrict__ cnt,
               size_t bStride, int biasStride, int listStride)
{
    extern __shared__ float smem[];
    int e = blockIdx.z;
    int Me = cnt[e];
    int m0 = blockIdx.y * 128;
    if (m0 >= Me) return;
    int n0 = blockIdx.x * 128;

    const float* Bp    = Bw + (size_t)e * bStride;
    const float* biasp = bias + (size_t)e * biasStride;
    const int*   gA    = gatherA  + (size_t)e * listStride;
    const int*   sC    = scatterC + (size_t)e * listStride;

    int tid = threadIdx.x, lane = tid & 31, warp = tid >> 5;
    int wm = warp >> 2, wn = warp & 3;
    int fr = lane >> 2, fc = lane & 3;

    int aRowBase = tid >> 3;           // +i*32
    int aKq = (tid & 7) * 4;
    const float* aSrc[4]; bool aValid[4];
#pragma unroll
    for (int i = 0; i < 4; i++) {
        int r = aRowBase + i*32;
        int rowA = m0 + r;
        aValid[i] = rowA < Me;
        aSrc[i] = aValid[i] ? (A + (size_t)gA[rowA]*K + aKq) : A;
    }
    int bKBase = tid >> 5;             // +i*8
    int bn4 = (tid & 31) * 4;
    const float* bSrc[4];
#pragma unroll
    for (int i = 0; i < 4; i++)
        bSrc[i] = Bp + (size_t)(bKBase + i*8)*N + n0 + bn4;

    float acc[4][4][4];
#pragma unroll
    for (int mi = 0; mi < 4; mi++)
#pragma unroll
        for (int ni = 0; ni < 4; ni++)
#pragma unroll
            for (int j = 0; j < 4; j++) acc[mi][ni][j] = 0.f;

    int nk = K >> 5;

    auto prefetch = [&](int s, int kt) {
        float* As_ = smem + s*STG_SZ;
        float* Bs_ = As_ + AS_SZ;
#pragma unroll
        for (int i = 0; i < 4; i++)
            cpasync16(As_ + (aRowBase + i*32)*36 + aKq,
                      aSrc[i] + (size_t)kt*32, aValid[i]);
#pragma unroll
        for (int i = 0; i < 4; i++)
            cpasync16(Bs_ + (bKBase + i*8)*136 + bn4,
                      bSrc[i] + (size_t)kt*32*N, true);
        asm volatile("cp.async.commit_group;\n");
    };

    prefetch(0, 0);

    for (int kt = 0; kt < nk; kt++) {
        int s = kt & 1;
        bool more = (kt + 1) < nk;
        if (more) prefetch(s ^ 1, kt + 1);
        if (more) asm volatile("cp.async.wait_group 1;\n");
        else      asm volatile("cp.async.wait_group 0;\n");
        __syncthreads();

        const float* As_ = smem + s*STG_SZ;
        const float* Bs_ = As_ + AS_SZ;
#pragma unroll
        for (int kk8 = 0; kk8 < 4; kk8++) {
            int kk = kk8 * 8;
            unsigned af[4][4], bf[4][2];
#pragma unroll
            for (int mi = 0; mi < 4; mi++) {
                int mb = wm*64 + mi*16;
                af[mi][0] = f2tf32(As_[(mb + fr    )*36 + kk + fc    ]);
                af[mi][1] = f2tf32(As_[(mb + fr + 8)*36 + kk + fc    ]);
                af[mi][2] = f2tf32(As_[(mb + fr    )*36 + kk + fc + 4]);
                af[mi][3] = f2tf32(As_[(mb + fr + 8)*36 + kk + fc + 4]);
            }
#pragma unroll
            for (int ni = 0; ni < 4; ni++) {
                int cb = wn*32 + ni*8;
                bf[ni][0] = f2tf32(Bs_[(kk + fc    )*136 + cb + fr]);
                bf[ni][1] = f2tf32(Bs_[(kk + fc + 4)*136 + cb + fr]);
            }
#pragma unroll
            for (int mi = 0; mi < 4; mi++)
#pragma unroll
                for (int ni = 0; ni < 4; ni++)
                    MMA_TF32(acc[mi][ni], af[mi][0],af[mi][1],af[mi][2],af[mi][3],
                             bf[ni][0], bf[ni][1]);
        }
        __syncthreads();
    }

#pragma unroll
    for (int mi = 0; mi < 4; mi++) {
        int rbase = m0 + wm*64 + mi*16 + fr;
#pragma unroll
        for (int half = 0; half < 2; half++) {
            int m = rbase + half*8;
            if (m >= Me) continue;
            int crow = sC[m];
#pragma unroll
            for (int ni = 0; ni < 4; ni++) {
                int n = n0 + wn*32 + ni*8 + fc*2;
                float v0 = acc[mi][ni][half*2 + 0] + biasp[n];
                float v1 = acc[mi][ni][half*2 + 1] + biasp[n+1];
                if (GELU) {
                    float u = v0;
                    v0 = 0.5f*u*(1.f + tanhf(0.7978845608028654f*(u + 0.044715f*u*u*u)));
                    u = v1;
                    v1 = 0.5f*u*(1.f + tanhf(0.7978845608028654f*(u + 0.044715f*u*u*u)));
                }
                *(float2*)(C + (size_t)crow * N + n) = make_float2(v0, v1);
            }
        }
    }
}

// ---------------------------------------------------------------- 3xTF32 dense GEMM v3
// fp32-grade GEMM: hi/lo split at fragment load; MMAs issued in 3 passes so
// dependent MMAs to the same accumulator are 16 apart (ILP).
template<bool RES>
__global__ void __launch_bounds__(256, 2)
mma3_kernel(const float* __restrict__ A,
            const float* __restrict__ Bw,
            const float* __restrict__ bias,
            const float* __restrict__ res,
            float* __restrict__ C,
            int N, int K)
{
    extern __shared__ float smem[];
    int m0 = blockIdx.y * 128;
    int n0 = blockIdx.x * 128;

    int tid = threadIdx.x, lane = tid & 31, warp = tid >> 5;
    int wm = warp >> 2, wn = warp & 3;
    int fr = lane >> 2, fc = lane & 3;

    int aRowBase = tid >> 3;
    int aKq = (tid & 7) * 4;
    const float* aSrc[4];
#pragma unroll
    for (int i = 0; i < 4; i++)
        aSrc[i] = A + (size_t)(m0 + aRowBase + i*32)*K + aKq;
    int bKBase = tid >> 5;
    int bn4 = (tid & 31) * 4;
    const float* bSrc[4];
#pragma unroll
    for (int i = 0; i < 4; i++)
        bSrc[i] = Bw + (size_t)(bKBase + i*8)*N + n0 + bn4;

    float acc[4][4][4];
#pragma unroll
    for (int mi = 0; mi < 4; mi++)
#pragma unroll
        for (int ni = 0; ni < 4; ni++)
#pragma unroll
            for (int j = 0; j < 4; j++) acc[mi][ni][j] = 0.f;

    int nk = K >> 5;

    auto prefetch = [&](int s, int kt) {
        float* As_ = smem + s*STG_SZ;
        float* Bs_ = As_ + AS_SZ;
#pragma unroll
        for (int i = 0; i < 4; i++)
            cpasync16(As_ + (aRowBase + i*32)*36 + aKq,
                      aSrc[i] + (size_t)kt*32, true);
#pragma unroll
        for (int i = 0; i < 4; i++)
            cpasync16(Bs_ + (bKBase + i*8)*136 + bn4,
                      bSrc[i] + (size_t)kt*32*N, true);
        asm volatile("cp.async.commit_group;\n");
    };

    prefetch(0, 0);

    for (int kt = 0; kt < nk; kt++) {
        int s = kt & 1;
        bool more = (kt + 1) < nk;
        if (more) prefetch(s ^ 1, kt + 1);
        if (more) asm volatile("cp.async.wait_group 1;\n");
        else      asm volatile("cp.async.wait_group 0;\n");
        __syncthreads();

        const float* As_ = smem + s*STG_SZ;
        const float* Bs_ = As_ + AS_SZ;
#pragma unroll
        for (int kk8 = 0; kk8 < 4; kk8++) {
            int kk = kk8 * 8;
            unsigned ah[4][4], al[4][4], bh[4][2], bl[4][2];
#pragma unroll
            for (int mi = 0; mi < 4; mi++) {
                int mb = wm*64 + mi*16;
                float v0 = As_[(mb + fr    )*36 + kk + fc    ];
                float v1 = As_[(mb + fr + 8)*36 + kk + fc    ];
                float v2 = As_[(mb + fr    )*36 + kk + fc + 4];
                float v3 = As_[(mb + fr + 8)*36 + kk + fc + 4];
                ah[mi][0] = f2tf32(v0); al[mi][0] = f2tf32(v0 - __uint_as_float(ah[mi][0]));
                ah[mi][1] = f2tf32(v1); al[mi][1] = f2tf32(v1 - __uint_as_float(ah[mi][1]));
                ah[mi][2] = f2tf32(v2); al[mi][2] = f2tf32(v2 - __uint_as_float(ah[mi][2]));
                ah[mi][3] = f2tf32(v3); al[mi][3] = f2tf32(v3 - __uint_as_float(ah[mi][3]));
            }
#pragma unroll
            for (int ni = 0; ni < 4; ni++) {
                int cb = wn*32 + ni*8;
                float u0 = Bs_[(kk + fc    )*136 + cb + fr];
                float u1 = Bs_[(kk + fc + 4)*136 + cb + fr];
                bh[ni][0] = f2tf32(u0); bl[ni][0] = f2tf32(u0 - __uint_as_float(bh[ni][0]));
                bh[ni][1] = f2tf32(u1); bl[ni][1] = f2tf32(u1 - __uint_as_float(bh[ni][1]));
            }
            // pass 1: hi*lo — all 16 accs (independent)
#pragma unroll
            for (int mi = 0; mi < 4; mi++)
#pragma unroll
                for (int ni = 0; ni < 4; ni++)
                    MMA_TF32(acc[mi][ni], ah[mi][0],ah[mi][1],ah[mi][2],ah[mi][3],
                             bl[ni][0], bl[ni][1]);
            // pass 2: lo*hi
#pragma unroll
            for (int mi = 0; mi < 4; mi++)
#pragma unroll
                for (int ni = 0; ni < 4; ni++)
                    MMA_TF32(acc[mi][ni], al[mi][0],al[mi][1],al[mi][2],al[mi][3],
                             bh[ni][0], bh[ni][1]);
            // pass 3: hi*hi
#pragma unroll
            for (int mi = 0; mi < 4; mi++)
#pragma unroll
                for (int ni = 0; ni < 4; ni++)
                    MMA_TF32(acc[mi][ni], ah[mi][0],ah[mi][1],ah[mi][2],ah[mi][3],
                             bh[ni][0], bh[ni][1]);
        }
        __syncthreads();
    }

#pragma unroll
    for (int mi = 0; mi < 4; mi++) {
        int rbase = m0 + wm*64 + mi*16 + fr;
#pragma unroll
        for (int half = 0; half < 2; half++) {
            int m = rbase + half*8;
#pragma unroll
            for (int ni = 0; ni < 4; ni++) {
                int n = n0 + wn*32 + ni*8 + fc*2;
                float v0 = acc[mi][ni][half*2 + 0] + bias[n];
                float v1 = acc[mi][ni][half*2 + 1] + bias[n+1];
                if (RES) {
                    v0 += res[(size_t)m * N + n];
                    v1 += res[(size_t)m * N + n + 1];
                }
                *(float2*)(C + (size_t)m * N + n) = make_float2(v0, v1);
            }
        }
    }
}

// ---------------------------------------------------------------- attention (tf32x3 flash)
// Block: 64 q-rows, 128 threads (4 warps, 16 q-rows each). K tiles of 64.
// MMAs grouped in fours: dependent MMAs to one acc are 4 apart.
__global__ void __launch_bounds__(128, 2)
attn_mma_kernel(const float* __restrict__ qkv, float* __restrict__ o)
{
    extern __shared__ float2 sm2[];
    float2* KT2 = sm2;               // [64][68]
    float2* V2  = sm2 + 64*68;       // [64][68]

    int qt = blockIdx.x, h = blockIdx.y, b = blockIdx.z;
    int tid = threadIdx.x;
    int lane = tid & 31, warp = tid >> 5;
    int fr = lane >> 2, fc = lane & 3;
    int w16 = warp * 16;
    size_t base = (size_t)b * S_ * (3*D_) + h*DH_;

    // ---- stage Q (scaled by 1/8) into V2 region as floats [q][68]
    float* Qs = (float*)V2;
#pragma unroll
    for (int rep = 0; rep < 8; rep++) {
        int lin = rep*512 + tid*4;
        int r = lin >> 6, d0 = lin & 63;
        float4 q = *(const float4*)(qkv + base + (size_t)(qt*64 + r)*(3*D_) + d0);
        Qs[r*68 + d0 + 0] = q.x * 0.125f;
        Qs[r*68 + d0 + 1] = q.y * 0.125f;
        Qs[r*68 + d0 + 2] = q.z * 0.125f;
        Qs[r*68 + d0 + 3] = q.w * 0.125f;
    }
    __syncthreads();

    // resident Q fragments (hi/lo)
    unsigned qh[8][4], ql[8][4];
#pragma unroll
    for (int kt = 0; kt < 8; kt++) {
        int c0 = kt*8 + fc;
        float v[4];
        v[0] = Qs[(w16+fr  )*68 + c0];
        v[1] = Qs[(w16+fr+8)*68 + c0];
        v[2] = Qs[(w16+fr  )*68 + c0 + 4];
        v[3] = Qs[(w16+fr+8)*68 + c0 + 4];
#pragma unroll
        for (int j = 0; j < 4; j++) {
            qh[kt][j] = f2tf32(v[j]);
            ql[kt][j] = f2tf32(v[j] - __uint_as_float(qh[kt][j]));
        }
    }

    float m0 = -1e30f, m1 = -1e30f, l0 = 0.f, l1 = 0.f;
    float oacc[8][4];
#pragma unroll
    for (int nt = 0; nt < 8; nt++)
#pragma unroll
        for (int j = 0; j < 4; j++) oacc[nt][j] = 0.f;

    for (int ktile = 0; ktile < S_/64; ktile++) {
        __syncthreads();   // prior O-phase reads (and Q staging reads) complete

        // ---- load K (transpose + swizzle + split) and V (split) ----
#pragma unroll
        for (int rep = 0; rep < 8; rep++) {
            int lin = rep*512 + tid*4;
            int r = lin >> 6, d0 = lin & 63;
            size_t row = base + (size_t)(ktile*64 + r)*(3*D_);
            float4 kv = *(const float4*)(qkv + row + D_ + d0);
            float kva[4] = {kv.x, kv.y, kv.z, kv.w};
#pragma unroll
            for (int i = 0; i < 4; i++) {
                int d = d0 + i;
                float hf = rndtf32(kva[i]);
                int col = r ^ ((d >> 2) & 15);
                KT2[d*68 + col] = make_float2(hf, kva[i] - hf);
            }
            float4 vv = *(const float4*)(qkv + row + 2*D_ + d0);
            float vva[4] = {vv.x, vv.y, vv.z, vv.w};
#pragma unroll
            for (int i = 0; i < 4; i++) {
                float hf = rndtf32(vva[i]);
                V2[r*68 + d0 + i] = make_float2(hf, vva[i] - hf);
            }
        }
        __syncthreads();

        // ---- S = Q K^T (tf32x3, grouped by 4 nt for ILP) ----
        float sacc[8][4];
#pragma unroll
        for (int nt = 0; nt < 8; nt++)
#pragma unroll
            for (int j = 0; j < 4; j++) sacc[nt][j] = 0.f;

#pragma unroll
        for (int kt = 0; kt < 8; kt++) {
            int d0 = kt*8 + fc, d1 = d0 + 4;
            int s0 = (d0 >> 2) & 15, s1 = (d1 >> 2) & 15;
#pragma unroll
            for (int ntg = 0; ntg < 8; ntg += 4) {
                unsigned Bh0[4], Bl0[4], Bh1[4], Bl1[4];
#pragma unroll
                for (int j = 0; j < 4; j++) {
                    int nt = ntg + j;
                    float2 b0 = KT2[d0*68 + ((nt*8 + fr) ^ s0)];
                    float2 b1 = KT2[d1*68 + ((nt*8 + fr) ^ s1)];
                    Bh0[j] = __float_as_uint(b0.x); Bl0[j] = __float_as_uint(b0.y);
                    Bh1[j] = __float_as_uint(b1.x); Bl1[j] = __float_as_uint(b1.y);
                }
#pragma unroll
                for (int j = 0; j < 4; j++)
                    MMA_TF32(sacc[ntg+j], qh[kt][0],qh[kt][1],qh[kt][2],qh[kt][3],
                             Bl0[j], Bl1[j]);
#pragma unroll
                for (int j = 0; j < 4; j++)
                    MMA_TF32(sacc[ntg+j], ql[kt][0],ql[kt][1],ql[kt][2],ql[kt][3],
                             Bh0[j], Bh1[j]);
#pragma unroll
                for (int j = 0; j < 4; j++)
                    MMA_TF32(sacc[ntg+j], qh[kt][0],qh[kt][1],qh[kt][2],qh[kt][3],
                             Bh0[j], Bh1[j]);
            }
        }

        // ---- online softmax (rows fr and fr+8 of this warp's 16) ----
        float rm0 = -1e30f, rm1 = -1e30f;
#pragma unroll
        for (int nt = 0; nt < 8; nt++) {
            rm0 = fmaxf(rm0, fmaxf(sacc[nt][0], sacc[nt][1]));
            rm1 = fmaxf(rm1, fmaxf(sacc[nt][2], sacc[nt][3]));
        }
        rm0 = fmaxf(rm0, __shfl_xor_sync(~0u, rm0, 1));
        rm0 = fmaxf(rm0, __shfl_xor_sync(~0u, rm0, 2));
        rm1 = fmaxf(rm1, __shfl_xor_sync(~0u, rm1, 1));
        rm1 = fmaxf(rm1, __shfl_xor_sync(~0u, rm1, 2));
        float mn0 = fmaxf(m0, rm0), mn1 = fmaxf(m1, rm1);
        float a0 = __expf(m0 - mn0), a1 = __expf(m1 - mn1);
        float sum0 = 0.f, sum1 = 0.f;
#pragma unroll
        for (int nt = 0; nt < 8; nt++) {
            sacc[nt][0] = __expf(sacc[nt][0] - mn0);
            sacc[nt][1] = __expf(sacc[nt][1] - mn0);
            sacc[nt][2] = __expf(sacc[nt][2] - mn1);
            sacc[nt][3] = __expf(sacc[nt][3] - mn1);
            sum0 += sacc[nt][0] + sacc[nt][1];
            sum1 += sacc[nt][2] + sacc[nt][3];
        }
        sum0 += __shfl_xor_sync(~0u, sum0, 1);
        sum0 += __shfl_xor_sync(~0u, sum0, 2);
        sum1 += __shfl_xor_sync(~0u, sum1, 1);
        sum1 += __shfl_xor_sync(~0u, sum1, 2);
        m0 = mn0; m1 = mn1;
        l0 = l0*a0 + sum0;
        l1 = l1*a1 + sum1;
#pragma unroll
        for (int nt = 0; nt < 8; nt++) {
            oacc[nt][0] *= a0; oacc[nt][1] *= a0;
            oacc[nt][2] *= a1; oacc[nt][3] *= a1;
        }

        __syncthreads();   // all S reads of KT2 done before P overwrite

        // ---- store P (hi/lo) into KT2 as [q][kseq], unswizzled ----
#pragma unroll
        for (int nt = 0; nt < 8; nt++) {
#pragma unroll
            for (int j = 0; j < 4; j++) {
                int row = w16 + fr + (j >> 1)*8;
                int col = nt*8 + 2*fc + (j & 1);
                float p = sacc[nt][j];
                float hf = rndtf32(p);
                KT2[row*68 + col] = make_float2(hf, p - hf);
            }
        }
        __syncthreads();

        // ---- O += P V (tf32x3, grouped by 4 nt) ----
#pragma unroll
        for (int kt = 0; kt < 8; kt++) {
            float2 A0 = KT2[(w16+fr  )*68 + kt*8 + fc    ];
            float2 A1 = KT2[(w16+fr+8)*68 + kt*8 + fc    ];
            float2 A2 = KT2[(w16+fr  )*68 + kt*8 + fc + 4];
            float2 A3 = KT2[(w16+fr+8)*68 + kt*8 + fc + 4];
            unsigned ph[4] = {__float_as_uint(A0.x), __float_as_uint(A1.x),
                              __float_as_uint(A2.x), __float_as_uint(A3.x)};
            unsigned pl[4] = {__float_as_uint(A0.y), __float_as_uint(A1.y),
                              __float_as_uint(A2.y), __float_as_uint(A3.y)};
#pragma unroll
            for (int ntg = 0; ntg < 8; ntg += 4) {
                unsigned Bh0[4], Bl0[4], Bh1[4], Bl1[4];
#pragma unroll
                for (int j = 0; j < 4; j++) {
                    int nt = ntg + j;
                    float2 b0 = V2[(kt*8 + fc    )*68 + nt*8 + fr];
                    float2 b1 = V2[(kt*8 + fc + 4)*68 + nt*8 + fr];
                    Bh0[j] = __float_as_uint(b0.x); Bl0[j] = __float_as_uint(b0.y);
                    Bh1[j] = __float_as_uint(b1.x); Bl1[j] = __float_as_uint(b1.y);
                }
#pragma unroll
                for (int j = 0; j < 4; j++)
                    MMA_TF32(oacc[ntg+j], ph[0],ph[1],ph[2],ph[3], Bl0[j], Bl1[j]);
#pragma unroll
                for (int j = 0; j < 4; j++)
                    MMA_TF32(oacc[ntg+j], pl[0],pl[1],pl[2],pl[3], Bh0[j], Bh1[j]);
#pragma unroll
                for (int j = 0; j < 4; j++)
                    MMA_TF32(oacc[ntg+j], ph[0],ph[1],ph[2],ph[3], Bh0[j], Bh1[j]);
            }
        }
    }

    // ---- finalize ----
    float inv0 = 1.f / l0, inv1 = 1.f / l1;
    int tok0 = b*S_ + qt*64 + w16 + fr;
#pragma unroll
    for (int nt = 0; nt < 8; nt++) {
        int col = h*DH_ + nt*8 + 2*fc;
        *(float2*)(o + (size_t)tok0*D_ + col) =
            make_float2(oacc[nt][0]*inv0, oacc[nt][1]*inv0);
        *(float2*)(o + (size_t)(tok0+8)*D_ + col) =
            make_float2(oacc[nt][2]*inv1, oacc[nt][3]*inv1);
    }
}

// ---------------------------------------------------------------- gate/top2
__global__ void gate_kernel(const float* __restrict__ xin,
                            const float* __restrict__ wg)
{
    int t = blockIdx.x;
    int tid = threadIdx.x;     // 128
    const float* xr = xin + (size_t)t * D_;
    float acc[E_] = {};
    for (int d = tid; d < D_; d += 128) {
        float xv = xr[d];
        const float* w = wg + d*E_;
#pragma unroll
        for (int e = 0; e < E_; e++) acc[e] = fmaf(xv, w[e], acc[e]);
    }
#pragma unroll
    for (int e = 0; e < E_; e++)
#pragma unroll
        for (int msk = 16; msk; msk >>= 1)
            acc[e] += __shfl_xor_sync(~0u, acc[e], msk);
    __shared__ float red[4][E_];
    if ((tid & 31) == 0)
#pragma unroll
        for (int e = 0; e < E_; e++) red[tid>>5][e] = acc[e];
    __syncthreads();
    if (tid == 0) {
        float lg[E_];
#pragma unroll
        for (int e = 0; e < E_; e++)
            lg[e] = red[0][e] + red[1][e] + red[2][e] + red[3][e];
        int i0 = 0;
#pragma unroll
        for (int e = 1; e < E_; e++) if (lg[e] > lg[i0]) i0 = e;
        int i1 = -1;
#pragma unroll
        for (int e = 0; e < E_; e++)
            if (e != i0 && (i1 < 0 || lg[e] > lg[i1])) i1 = e;
        float d10 = __expf(lg[i1] - lg[i0]);        // <= 1
        float w0 = 1.f / (1.f + d10);
        float w1 = d10 * w0;
        g_tokW[2*t]   = w0;
        g_tokW[2*t+1] = w1;
        int p0 = atomicAdd(&g_cnt[i0], 1);
        g_exTok[i0*T_ + p0] = t;  g_exDst[i0*T_ + p0] = 2*t;
        int p1 = atomicAdd(&g_cnt[i1], 1);
        g_exTok[i1*T_ + p1] = t;  g_exDst[i1*T_ + p1] = 2*t+1;
    }
}

// ---------------------------------------------------------------- combine
__global__ void combine_kernel(const float* __restrict__ x1,
                               float* __restrict__ out)
{
    size_t idx = ((size_t)blockIdx.x * 256 + threadIdx.x) * 4;
    if (idx >= (size_t)T_*D_) return;
    int t = (int)(idx >> 10);
    int c = (int)(idx & (D_-1));
    float w0 = g_tokW[2*t], w1 = g_tokW[2*t+1];
    float4 a  = *(const float4*)(x1 + idx);
    float4 y0 = *(const float4*)(g_ybuf + (size_t)(2*t)*D_ + c);
    float4 y1 = *(const float4*)(g_ybuf + (size_t)(2*t+1)*D_ + c);
    float4 r;
    r.x = a.x + w0*y0.x + w1*y1.x;
    r.y = a.y + w0*y0.y + w1*y1.y;
    r.z = a.z + w0*y0.z + w1*y1.z;
    r.w = a.w + w0*y0.w + w1*y1.w;
    *(float4*)(out + idx) = r;
}

// ---------------------------------------------------------------- launch
extern "C" void kernel_launch(void* const* d_in, const int* in_sizes, int n_in,
                              void* d_out, int out_size)
{
    const float* x      = (const float*)d_in[0];
    const float* ln1_g  = (const float*)d_in[1];
    const float* ln1_b  = (const float*)d_in[2];
    const float* ln2_g  = (const float*)d_in[3];
    const float* ln2_b  = (const float*)d_in[4];
    const float* w_qkv  = (const float*)d_in[5];
    const float* b_qkv  = (const float*)d_in[6];
    const float* w_out  = (const float*)d_in[7];
    const float* b_out  = (const float*)d_in[8];
    const float* w_gate = (const float*)d_in[9];
    const float* w1     = (const float*)d_in[10];
    const float* b1     = (const float*)d_in[11];
    const float* w2     = (const float*)d_in[12];
    const float* b2     = (const float*)d_in[13];
    float* out = (float*)d_out;

    float *p_h, *p_qkv, *p_attn, *p_x1, *p_moein, *p_he, *p_ybuf;
    int *p_exTok, *p_exDst, *p_cnt;
    cudaGetSymbolAddress((void**)&p_h,     g_h);
    cudaGetSymbolAddress((void**)&p_qkv,   g_qkv);
    cudaGetSymbolAddress((void**)&p_attn,  g_attn);
    cudaGetSymbolAddress((void**)&p_x1,    g_x1);
    cudaGetSymbolAddress((void**)&p_moein, g_moein);
    cudaGetSymbolAddress((void**)&p_he,    g_he);
    cudaGetSymbolAddress((void**)&p_ybuf,  g_ybuf);
    cudaGetSymbolAddress((void**)&p_exTok, g_exTok);
    cudaGetSymbolAddress((void**)&p_exDst, g_exDst);
    cudaGetSymbolAddress((void**)&p_cnt,   g_cnt);

    cudaFuncSetAttribute(moe_mma_kernel<true>,
        cudaFuncAttributeMaxDynamicSharedMemorySize, DSMEM_BYTES);
    cudaFuncSetAttribute(moe_mma_kernel<false>,
        cudaFuncAttributeMaxDynamicSharedMemorySize, DSMEM_BYTES);
    cudaFuncSetAttribute(mma3_kernel<false>,
        cudaFuncAttributeMaxDynamicSharedMemorySize, DSMEM_BYTES);
    cudaFuncSetAttribute(mma3_kernel<true>,
        cudaFuncAttributeMaxDynamicSharedMemorySize, DSMEM_BYTES);
    cudaFuncSetAttribute(attn_mma_kernel,
        cudaFuncAttributeMaxDynamicSharedMemorySize, ATTN_SMEM);

    zero_cnt_kernel<<<1, 32>>>();

    // LN1
    ln_kernel<<<T_, 256>>>(x, ln1_g, ln1_b, p_h);

    // QKV (3xTF32, fp32-grade)
    mma3_kernel<false><<<dim3(3*D_/128, T_/128, 1), 256, DSMEM_BYTES>>>(
        p_h, w_qkv, b_qkv, nullptr, p_qkv, 3*D_, D_);

    // attention (tf32x3 flash)
    attn_mma_kernel<<<dim3(S_/64, H_, B_), 128, ATTN_SMEM>>>(p_qkv, p_attn);

    // out-proj + residual (3xTF32)
    mma3_kernel<true><<<dim3(D_/128, T_/128, 1), 256, DSMEM_BYTES>>>(
        p_attn, w_out, b_out, x, p_x1, D_, D_);

    // LN2
    ln_kernel<<<T_, 256>>>(p_x1, ln2_g, ln2_b, p_moein);

    // gate + routing (fp32, reads unrounded moein)
    gate_kernel<<<T_, 128>>>(p_moein, w_gate);

    // expert GEMM1: he = gelu(rnd(gather(moein)) @ rnd(w1) + b1)
    moe_mma_kernel<true><<<dim3(DFF_/128, T_/128, E_), 256, DSMEM_BYTES>>>(
        p_moein, w1, b1, p_he,
        DFF_, D_, p_exTok, p_exDst, p_cnt,
        (size_t)D_*DFF_, DFF_, T_);

    // expert GEMM2: ybuf = rnd(gather(he)) @ rnd(w2) + b2
    moe_mma_kernel<false><<<dim3(D_/128, T_/128, E_), 256, DSMEM_BYTES>>>(
        p_he, w2, b2, p_ybuf,
        D_, DFF_, p_exDst, p_exDst, p_cnt,
        (size_t)DFF_*D_, D_, T_);

    // combine: out = x1 + w0*y0 + w1*y1
    combine_kernel<<<(T_*D_/4 + 255)/256, 256>>>(p_x1, out);
}